// round 9
// baseline (speedup 1.0000x reference)
#include <cuda_runtime.h>
#include <cuda_bf16.h>
#include <cuda_fp16.h>
#include <cstdint>
#include <cstddef>

// Problem constants (fixed by the dataset)
#define NN 64000
#define EE 1048576
#define NG 64
#define NBN 1000
#define F_IN 128
#define H1 256
#define H2 256
#define H3 128
#define OUTD 64

// -------------------- scratch (device globals; no allocs) --------------------
__device__ __align__(16) float g_bufA[(size_t)NN * 256];          // fp32 h3 for FC
__device__ __align__(16) __nv_bfloat16 g_ahi[(size_t)NN * 256];   // GEMM A hi
__device__ __align__(16) __nv_bfloat16 g_alo[(size_t)NN * 256];   // GEMM A lo
__device__ __align__(16) __half g_hf[(size_t)NN * 256];           // fp16 activations (gather src)
__device__ __align__(16) __nv_bfloat16 g_wtH[256 * 256];          // W hi, [k][n]
__device__ __align__(16) __nv_bfloat16 g_wtL[256 * 256];          // W lo, [k][n]
__device__ int2  g_edge[EE];                                      // {src, w = dinv[d]*dinv[s]}
__device__ int   g_counts[NN];
__device__ int   g_offsets[NN + 1];
__device__ int   g_fill[NN];
__device__ float g_dinv[NN];
__device__ int   g_isI64;
__device__ int   g_bsum[256];
__device__ int   g_boff[256];

__device__ __forceinline__ int ei_at(const void* ei, size_t idx) {
    if (g_isI64) return (int)((const long long*)ei)[idx];
    return ((const int*)ei)[idx];
}

// -------------------- PTX helpers (family-generic sm_80+ features only) ------
__device__ __forceinline__ uint32_t smem_u32(const void* p) {
    uint32_t a;
    asm("{ .reg .u64 t; cvta.to.shared.u64 t, %1; cvt.u32.u64 %0, t; }" : "=r"(a) : "l"(p));
    return a;
}
#define LDSM_X4(r, a)                                                              \
    asm volatile("ldmatrix.sync.aligned.m8n8.x4.shared.b16 {%0,%1,%2,%3}, [%4];"   \
                 : "=r"((r)[0]), "=r"((r)[1]), "=r"((r)[2]), "=r"((r)[3]) : "r"(a))
#define LDSM_X4T(r, a)                                                                  \
    asm volatile("ldmatrix.sync.aligned.m8n8.x4.trans.shared.b16 {%0,%1,%2,%3}, [%4];"  \
                 : "=r"((r)[0]), "=r"((r)[1]), "=r"((r)[2]), "=r"((r)[3]) : "r"(a))

__device__ __forceinline__ void mma16816(float* c, const uint32_t* a,
                                         uint32_t b0, uint32_t b1) {
    asm volatile(
        "mma.sync.aligned.m16n8k16.row.col.f32.bf16.bf16.f32 "
        "{%0,%1,%2,%3}, {%4,%5,%6,%7}, {%8,%9}, {%0,%1,%2,%3};"
        : "+f"(c[0]), "+f"(c[1]), "+f"(c[2]), "+f"(c[3])
        : "r"(a[0]), "r"(a[1]), "r"(a[2]), "r"(a[3]), "r"(b0), "r"(b1));
}

// pack 2 floats -> bf16x2 (v0 in low half), and produce the lo-residual pack
__device__ __forceinline__ uint32_t pack_split(float v0, float v1, uint32_t& lopack) {
    uint32_t h;
    asm("cvt.rn.bf16x2.f32 %0, %1, %2;" : "=r"(h) : "f"(v1), "f"(v0));
    float h0 = __uint_as_float(h << 16);
    float h1 = __uint_as_float(h & 0xffff0000u);
    float l0 = v0 - h0, l1 = v1 - h1;
    asm("cvt.rn.bf16x2.f32 %0, %1, %2;" : "=r"(lopack) : "f"(l1), "f"(l0));
    return h;
}
__device__ __forceinline__ float2 h2f2(uint32_t u) {
    return __half22float2(*(__half2*)&u);
}

// -------------------- dtype detection --------------------
__global__ void detect_kernel(const void* ei) {
    const unsigned int* w = (const unsigned int*)ei;
    int is64 = 1;
    #pragma unroll
    for (int i = 0; i < 32; i++)
        if (w[2 * i + 1] != 0u) is64 = 0;
    g_isI64 = is64;
}

// -------------------- preprocessing --------------------
__global__ void zero_kernel() {
    int i = blockIdx.x * blockDim.x + threadIdx.x;
    if (i < NN) { g_fill[i] = 0; g_counts[i] = 0; }
}

__global__ void hist_kernel(const void* __restrict__ ei) {
    int e = blockIdx.x * blockDim.x + threadIdx.x;
    if (e < EE) {
        int d = ei_at(ei, (size_t)EE + e);
        atomicAdd(&g_counts[d], 1);
    }
}

__global__ void reduce_kernel() {
    int b = blockIdx.x;
    int v = g_counts[b * 256 + threadIdx.x];
    #pragma unroll
    for (int o = 16; o; o >>= 1) v += __shfl_down_sync(0xffffffffu, v, o);
    __shared__ int ws[8];
    if ((threadIdx.x & 31) == 0) ws[threadIdx.x >> 5] = v;
    __syncthreads();
    if (threadIdx.x == 0) {
        int s = 0;
        #pragma unroll
        for (int i = 0; i < 8; i++) s += ws[i];
        g_bsum[b] = s;
    }
}

__global__ void scanpart_kernel() {
    int t = threadIdx.x;
    int v = (t < NN / 256) ? g_bsum[t] : 0;
    int lane = t & 31, w = t >> 5;
    int x = v;
    #pragma unroll
    for (int o = 1; o < 32; o <<= 1) {
        int y = __shfl_up_sync(0xffffffffu, x, o);
        if (lane >= o) x += y;
    }
    __shared__ int ws[8], wso[8];
    if (lane == 31) ws[w] = x;
    __syncthreads();
    if (t < 8) {
        int s = 0;
        for (int i = 0; i < t; i++) s += ws[i];
        wso[t] = s;
    }
    __syncthreads();
    int incl = x + wso[w];
    if (t < NN / 256) g_boff[t] = incl - v;
    if (t == 255) g_offsets[NN] = incl;
}

__global__ void blockscan_kernel() {
    int b = blockIdx.x, t = threadIdx.x, i = b * 256 + t;
    int c = g_counts[i];
    int lane = t & 31, w = t >> 5;
    int x = c;
    #pragma unroll
    for (int o = 1; o < 32; o <<= 1) {
        int y = __shfl_up_sync(0xffffffffu, x, o);
        if (lane >= o) x += y;
    }
    __shared__ int ws[8], wso[8];
    if (lane == 31) ws[w] = x;
    __syncthreads();
    if (t < 8) {
        int s = 0;
        for (int j = 0; j < t; j++) s += ws[j];
        wso[t] = s;
    }
    __syncthreads();
    g_offsets[i] = x - c + wso[w] + g_boff[b];
    g_dinv[i] = rsqrtf((float)(c + 1));
}

// scatter dst-sorted edge records {src, dinv[d]*dinv[s]} (needs g_dinv ready)
__global__ void scatter_kernel(const void* __restrict__ ei) {
    int e = blockIdx.x * blockDim.x + threadIdx.x;
    if (e < EE) {
        int d = ei_at(ei, (size_t)EE + e);
        int s = ei_at(ei, (size_t)e);
        int pos = g_offsets[d] + atomicAdd(&g_fill[d], 1);
        float w = g_dinv[d] * g_dinv[s];
        g_edge[pos] = make_int2(s, __float_as_int(w));
    }
}

// -------------------- x -> fp16 --------------------
__global__ void xconv_kernel(const float* __restrict__ x) {
    int i = blockIdx.x * blockDim.x + threadIdx.x;  // over NN*F_IN/2
    if (i < NN * F_IN / 2) {
        float2 v = ((const float2*)x)[i];
        ((__half2*)g_hf)[i] = __floats2half2_rn(v.x, v.y);
    }
}

// -------------------- weight split: Whi/Wlo[k][n] (layout preserved) ---------
template <int K, int NOUT>
__global__ void splitw_kernel(const float* __restrict__ W) {
    int i = blockIdx.x * blockDim.x + threadIdx.x;
    if (i >= K * NOUT) return;
    float v = W[i];
    __nv_bfloat16 h = __float2bfloat16(v);
    g_wtH[i] = h;
    g_wtL[i] = __float2bfloat16(v - __bfloat162float(h));
}

// -------------------- aggregation: smem-resident graph quarter ---------------
// grid = NG * (H/64) CTAs; CTA loads its graph's 64-col feature quarter (fp16,
// 128 B/node -> 128 KB) + nothing else per edge but an 8B broadcast LDG.
// warp-per-dst-node gather from smem (conflict-free: 32 lanes x 4B, one row).
// Output: split bf16 hi/lo (GEMM A input), fp32 accumulation throughout.
#define AGG_SM (NBN * 128 + NBN * 4)
template <int H>
__global__ void __launch_bounds__(1024, 1)
aggsm_kernel() {
    extern __shared__ char sm[];
    float* sdv = (float*)(sm + NBN * 128);

    const int t = threadIdx.x;
    const int g = blockIdx.x / (H / 64);
    const int q = blockIdx.x % (H / 64);
    const int base = g * NBN;

    // load feature quarter: node row = 128 B (8 x uint4), coalesced
    for (int i = t; i < NBN * 8; i += 1024) {
        int row = i >> 3, seg = i & 7;
        ((uint4*)sm)[i] =
            ((const uint4*)(g_hf + (size_t)(base + row) * H + q * 64))[seg];
    }
    for (int i = t; i < NBN; i += 1024) sdv[i] = g_dinv[base + i];
    __syncthreads();

    const int warp = t >> 5, lane = t & 31;
    for (int n = warp; n < NBN; n += 32) {
        const int ng = base + n;
        const float dd = sdv[n];
        const float w0 = dd * dd;

        float2 f = h2f2(*(const uint32_t*)(sm + n * 128 + lane * 4));
        float a0 = w0 * f.x, a1 = w0 * f.y;

        const int e0 = g_offsets[ng], e1 = g_offsets[ng + 1];
        for (int e = e0; e < e1; e++) {
            int2 ew = g_edge[e];                   // broadcast LDG.64
            int sl = ew.x - base;
            float w = __int_as_float(ew.y);
            float2 fv = h2f2(*(const uint32_t*)(sm + sl * 128 + lane * 4));
            a0 += w * fv.x;
            a1 += w * fv.y;
        }

        uint32_t lo;
        uint32_t hi = pack_split(a0, a1, lo);
        size_t o = (size_t)ng * H + q * 64 + 2 * lane;
        *(uint32_t*)(g_ahi + o) = hi;
        *(uint32_t*)(g_alo + o) = lo;
    }
}

// -------------------- GEMM via mma.sync (HMMA): C = A(split) @ W(split) ------
// CTA tile 128x128, 8 warps (4x2), warp tile 32x64, k-chunk 64.
// Epilogue: v = tanh(acc + bias). HALFOUT=1 -> g_hf fp16; else fp32 g_bufA.
#define A_PITCH 144   // 64 bf16 = 128B + 16B pad
#define B_PITCH 272   // 128 bf16 = 256B + 16B pad
#define SM_AH 0
#define SM_AL (128 * A_PITCH)
#define SM_BH (2 * 128 * A_PITCH)
#define SM_BL (2 * 128 * A_PITCH + 64 * B_PITCH)
#define SM_TOT (2 * 128 * A_PITCH + 2 * 64 * B_PITCH)

template <int K, int NB, int HALFOUT>
__global__ void __launch_bounds__(256, 1)
gemm_mma(const float* __restrict__ bias) {
    extern __shared__ char sm[];
    const int t = threadIdx.x;
    const int warp = t >> 5, lane = t & 31;
    const int wm = warp >> 1, wn = warp & 1;
    const int m0 = blockIdx.y * 128, n0 = blockIdx.x * 128;

    float c[2][8][4];
    #pragma unroll
    for (int i = 0; i < 2; i++)
        #pragma unroll
        for (int j = 0; j < 8; j++)
            #pragma unroll
            for (int q = 0; q < 4; q++) c[i][j][q] = 0.0f;

    for (int ch = 0; ch < K / 64; ch++) {
        const int k0 = ch * 64;
        #pragma unroll
        for (int i = 0; i < 4; i++) {
            int idx = t + i * 256;
            int row = idx >> 3, seg = idx & 7;
            size_t gofs = ((size_t)(m0 + row) * K + k0) * 2 + seg * 16;
            *(uint4*)(sm + SM_AH + row * A_PITCH + seg * 16) =
                *(const uint4*)((const char*)g_ahi + gofs);
            *(uint4*)(sm + SM_AL + row * A_PITCH + seg * 16) =
                *(const uint4*)((const char*)g_alo + gofs);
        }
        #pragma unroll
        for (int i = 0; i < 4; i++) {
            int idx = t + i * 256;
            int row = idx >> 4, seg = idx & 15;
            size_t gofs = ((size_t)(k0 + row) * NB + n0) * 2 + seg * 16;
            *(uint4*)(sm + SM_BH + row * B_PITCH + seg * 16) =
                *(const uint4*)((const char*)g_wtH + gofs);
            *(uint4*)(sm + SM_BL + row * B_PITCH + seg * 16) =
                *(const uint4*)((const char*)g_wtL + gofs);
        }
        __syncthreads();

        #pragma unroll
        for (int k16 = 0; k16 < 4; k16++) {
            uint32_t ah[2][4], al[2][4];
            #pragma unroll
            for (int mt = 0; mt < 2; mt++) {
                int row = wm * 32 + mt * 16 + (lane & 15);
                int cb = k16 * 32 + ((lane >> 4) << 4);
                LDSM_X4(ah[mt], smem_u32(sm + SM_AH + row * A_PITCH + cb));
                LDSM_X4(al[mt], smem_u32(sm + SM_AL + row * A_PITCH + cb));
            }
            uint32_t bh[4][4], bl[4][4];
            #pragma unroll
            for (int np = 0; np < 4; np++) {
                int krow = k16 * 16 + (lane & 7) + (lane & 8);
                int cb = wn * 128 + np * 32 + ((lane >> 4) << 4);
                LDSM_X4T(bh[np], smem_u32(sm + SM_BH + krow * B_PITCH + cb));
                LDSM_X4T(bl[np], smem_u32(sm + SM_BL + krow * B_PITCH + cb));
            }
            #pragma unroll
            for (int mt = 0; mt < 2; mt++) {
                #pragma unroll
                for (int np = 0; np < 4; np++) {
                    mma16816(c[mt][np * 2],     ah[mt], bh[np][0], bh[np][1]);
                    mma16816(c[mt][np * 2],     al[mt], bh[np][0], bh[np][1]);
                    mma16816(c[mt][np * 2],     ah[mt], bl[np][0], bl[np][1]);
                    mma16816(c[mt][np * 2 + 1], ah[mt], bh[np][2], bh[np][3]);
                    mma16816(c[mt][np * 2 + 1], al[mt], bh[np][2], bh[np][3]);
                    mma16816(c[mt][np * 2 + 1], ah[mt], bl[np][2], bl[np][3]);
                }
            }
        }
        __syncthreads();
    }

    // epilogue: tanh(acc + bias) -> fp16 (for gather) or fp32 (for FC)
    const int g = lane >> 2, tq = lane & 3;
    #pragma unroll
    for (int mt = 0; mt < 2; mt++) {
        int row = m0 + wm * 32 + mt * 16 + g;
        #pragma unroll
        for (int n8 = 0; n8 < 8; n8++) {
            int col = n0 + wn * 64 + n8 * 8 + 2 * tq;
            float b0 = __ldg(bias + col), b1 = __ldg(bias + col + 1);
            float v0 = tanhf(c[mt][n8][0] + b0);
            float v1 = tanhf(c[mt][n8][1] + b1);
            float v2 = tanhf(c[mt][n8][2] + b0);
            float v3 = tanhf(c[mt][n8][3] + b1);
            if (HALFOUT) {
                *(__half2*)(g_hf + (size_t)row * NB + col) = __floats2half2_rn(v0, v1);
                *(__half2*)(g_hf + (size_t)(row + 8) * NB + col) = __floats2half2_rn(v2, v3);
            } else {
                *(float2*)(g_bufA + (size_t)row * NB + col) = make_float2(v0, v1);
                *(float2*)(g_bufA + (size_t)(row + 8) * NB + col) = make_float2(v2, v3);
            }
        }
    }
}

// -------------------- final FC: out[64,64] = h3.reshape(64,128000) @ Wfc + bfc
__global__ void fc_init(const float* __restrict__ bfc, float* __restrict__ out) {
    int i = blockIdx.x * blockDim.x + threadIdx.x;
    if (i < NG * OUTD) out[i] = bfc[i & 63];
}

#define FC_KCH 1024
__global__ void fc_kernel(const float* __restrict__ Wfc,
                          float* __restrict__ out) {
    const float* __restrict__ h3 = g_bufA;
    __shared__ float Ws[16][64];
    __shared__ float Hs[64][17];
    const int t = threadIdx.x;
    const int tg = t & 15;
    const int to = t >> 4;
    float acc[4][4];
    #pragma unroll
    for (int i = 0; i < 4; i++)
        #pragma unroll
        for (int j = 0; j < 4; j++) acc[i][j] = 0.0f;

    const int kbase = blockIdx.x * FC_KCH;
    for (int kk0 = 0; kk0 < FC_KCH; kk0 += 16) {
        const int k0 = kbase + kk0;
        #pragma unroll
        for (int rr = 0; rr < 4; rr++) {
            int idx = t + rr * 256;
            int kr = idx >> 6, nn = idx & 63;
            Ws[kr][nn] = Wfc[(size_t)(k0 + kr) * OUTD + nn];
        }
        #pragma unroll
        for (int rr = 0; rr < 4; rr++) {
            int idx = t + rr * 256;
            int g = idx >> 4, kk = idx & 15;
            Hs[g][kk] = h3[(size_t)g * 128000 + k0 + kk];
        }
        __syncthreads();
        #pragma unroll
        for (int kk = 0; kk < 16; kk++) {
            float hv[4], wv[4];
            #pragma unroll
            for (int i = 0; i < 4; i++) hv[i] = Hs[4 * tg + i][kk];
            #pragma unroll
            for (int j = 0; j < 4; j++) wv[j] = Ws[kk][4 * to + j];
            #pragma unroll
            for (int i = 0; i < 4; i++)
                #pragma unroll
                for (int j = 0; j < 4; j++) acc[i][j] += hv[i] * wv[j];
        }
        __syncthreads();
    }
    #pragma unroll
    for (int i = 0; i < 4; i++)
        #pragma unroll
        for (int j = 0; j < 4; j++)
            atomicAdd(&out[(4 * tg + i) * OUTD + 4 * to + j], acc[i][j]);
}

// -------------------- launch --------------------
extern "C" void kernel_launch(void* const* d_in, const int* in_sizes, int n_in,
                              void* d_out, int out_size) {
    const float* x   = (const float*)d_in[0];
    const void*  ei  = d_in[1];
    const float* W1  = (const float*)d_in[3];
    const float* b1  = (const float*)d_in[4];
    const float* W2  = (const float*)d_in[5];
    const float* b2  = (const float*)d_in[6];
    const float* W3  = (const float*)d_in[7];
    const float* b3  = (const float*)d_in[8];
    const float* Wfc = (const float*)d_in[9];
    const float* bfc = (const float*)d_in[10];
    float* out = (float*)d_out;

    cudaFuncSetAttribute(gemm_mma<F_IN, H1, 1>, cudaFuncAttributeMaxDynamicSharedMemorySize, SM_TOT);
    cudaFuncSetAttribute(gemm_mma<H1, H2, 1>,   cudaFuncAttributeMaxDynamicSharedMemorySize, SM_TOT);
    cudaFuncSetAttribute(gemm_mma<H2, H3, 0>,   cudaFuncAttributeMaxDynamicSharedMemorySize, SM_TOT);
    cudaFuncSetAttribute(aggsm_kernel<F_IN>, cudaFuncAttributeMaxDynamicSharedMemorySize, AGG_SM);
    cudaFuncSetAttribute(aggsm_kernel<H1>,   cudaFuncAttributeMaxDynamicSharedMemorySize, AGG_SM);

    // preprocessing
    detect_kernel<<<1, 1>>>(ei);
    zero_kernel<<<(NN + 255) / 256, 256>>>();
    hist_kernel<<<EE / 256, 256>>>(ei);
    reduce_kernel<<<NN / 256, 256>>>();
    scanpart_kernel<<<1, 256>>>();
    blockscan_kernel<<<NN / 256, 256>>>();
    scatter_kernel<<<EE / 256, 256>>>(ei);
    xconv_kernel<<<(NN * F_IN / 2 + 255) / 256, 256>>>(x);

    // layer 1: smem-agg (Â x, fp16) then GEMM(128->256), tanh -> fp16
    splitw_kernel<F_IN, H1><<<(F_IN * H1 + 255) / 256, 256>>>(W1);
    aggsm_kernel<F_IN><<<NG * (F_IN / 64), 1024, AGG_SM>>>();
    gemm_mma<F_IN, H1, 1><<<dim3(H1 / 128, NN / 128), 256, SM_TOT>>>(b1);

    // layer 2: smem-agg (256) then GEMM(256->256), tanh -> fp16
    splitw_kernel<H1, H2><<<(H1 * H2 + 255) / 256, 256>>>(W2);
    aggsm_kernel<H1><<<NG * (H1 / 64), 1024, AGG_SM>>>();
    gemm_mma<H1, H2, 1><<<dim3(H2 / 128, NN / 128), 256, SM_TOT>>>(b2);

    // layer 3: smem-agg then GEMM(256->128), tanh -> fp32 for FC
    splitw_kernel<H2, H3><<<(H2 * H3 + 255) / 256, 256>>>(W3);
    aggsm_kernel<H2><<<NG * (H2 / 64), 1024, AGG_SM>>>();
    gemm_mma<H2, H3, 0><<<dim3(H3 / 128, NN / 128), 256, SM_TOT>>>(b3);

    // final FC with split-K atomics
    fc_init<<<(NG * OUTD + 255) / 256, 256>>>(bfc, out);
    fc_kernel<<<128000 / FC_KCH, 256>>>(Wfc, out);
}

// round 10
// speedup vs baseline: 1.2223x; 1.2223x over previous
#include <cuda_runtime.h>
#include <cuda_bf16.h>
#include <cuda_fp16.h>
#include <cstdint>
#include <cstddef>

// Problem constants (fixed by the dataset)
#define NN 64000
#define EE 1048576
#define NG 64
#define NBN 1000
#define F_IN 128
#define H1 256
#define H2 256
#define H3 128
#define OUTD 64

// -------------------- scratch (device globals; no allocs) --------------------
__device__ __align__(16) float g_bufA[(size_t)NN * 256];          // fp32 h3 for FC
__device__ __align__(16) __nv_bfloat16 g_ahi[(size_t)NN * 256];   // GEMM A hi
__device__ __align__(16) __nv_bfloat16 g_alo[(size_t)NN * 256];   // GEMM A lo
__device__ __align__(16) __half g_hf[(size_t)NN * 256];           // fp16 activations (gather src)
__device__ __align__(16) __nv_bfloat16 g_wtH[256 * 256];          // W hi, [k][n]
__device__ __align__(16) __nv_bfloat16 g_wtL[256 * 256];          // W lo, [k][n]
__device__ int2  g_edge[EE];                                      // {src, w = dinv[d]*dinv[s]}
__device__ int   g_counts[NN];
__device__ int   g_offsets[NN + 1];
__device__ int   g_fill[NN];
__device__ float g_dinv[NN];
__device__ int   g_isI64;
__device__ int   g_bsum[256];
__device__ int   g_boff[256];

__device__ __forceinline__ int ei_at(const void* ei, size_t idx) {
    if (g_isI64) return (int)((const long long*)ei)[idx];
    return ((const int*)ei)[idx];
}

// -------------------- PTX helpers (family-generic sm_80+ features only) ------
__device__ __forceinline__ uint32_t smem_u32(const void* p) {
    uint32_t a;
    asm("{ .reg .u64 t; cvta.to.shared.u64 t, %1; cvt.u32.u64 %0, t; }" : "=r"(a) : "l"(p));
    return a;
}
__device__ __forceinline__ void cpa16(uint32_t s, const void* g) {
    asm volatile("cp.async.cg.shared.global [%0], [%1], 16;" :: "r"(s), "l"(g) : "memory");
}
#define CPA_COMMIT() asm volatile("cp.async.commit_group;" ::: "memory")
#define CPA_WAIT0()  asm volatile("cp.async.wait_group 0;" ::: "memory")

#define LDSM_X4(r, a)                                                              \
    asm volatile("ldmatrix.sync.aligned.m8n8.x4.shared.b16 {%0,%1,%2,%3}, [%4];"   \
                 : "=r"((r)[0]), "=r"((r)[1]), "=r"((r)[2]), "=r"((r)[3]) : "r"(a))
#define LDSM_X4T(r, a)                                                                  \
    asm volatile("ldmatrix.sync.aligned.m8n8.x4.trans.shared.b16 {%0,%1,%2,%3}, [%4];"  \
                 : "=r"((r)[0]), "=r"((r)[1]), "=r"((r)[2]), "=r"((r)[3]) : "r"(a))

__device__ __forceinline__ void mma16816(float* c, const uint32_t* a,
                                         uint32_t b0, uint32_t b1) {
    asm volatile(
        "mma.sync.aligned.m16n8k16.row.col.f32.bf16.bf16.f32 "
        "{%0,%1,%2,%3}, {%4,%5,%6,%7}, {%8,%9}, {%0,%1,%2,%3};"
        : "+f"(c[0]), "+f"(c[1]), "+f"(c[2]), "+f"(c[3])
        : "r"(a[0]), "r"(a[1]), "r"(a[2]), "r"(a[3]), "r"(b0), "r"(b1));
}

// pack 2 floats -> bf16x2 (v0 in low half), and produce the lo-residual pack
__device__ __forceinline__ uint32_t pack_split(float v0, float v1, uint32_t& lopack) {
    uint32_t h;
    asm("cvt.rn.bf16x2.f32 %0, %1, %2;" : "=r"(h) : "f"(v1), "f"(v0));
    float h0 = __uint_as_float(h << 16);
    float h1 = __uint_as_float(h & 0xffff0000u);
    float l0 = v0 - h0, l1 = v1 - h1;
    asm("cvt.rn.bf16x2.f32 %0, %1, %2;" : "=r"(lopack) : "f"(l1), "f"(l0));
    return h;
}
__device__ __forceinline__ float2 h2f2(uint32_t u) {
    return __half22float2(*(__half2*)&u);
}

// -------------------- dtype detection --------------------
__global__ void detect_kernel(const void* ei) {
    const unsigned int* w = (const unsigned int*)ei;
    int is64 = 1;
    #pragma unroll
    for (int i = 0; i < 32; i++)
        if (w[2 * i + 1] != 0u) is64 = 0;
    g_isI64 = is64;
}

// -------------------- preprocessing --------------------
__global__ void zero_kernel() {
    int i = blockIdx.x * blockDim.x + threadIdx.x;
    if (i < NN) { g_fill[i] = 0; g_counts[i] = 0; }
}

__global__ void hist_kernel(const void* __restrict__ ei) {
    int e = blockIdx.x * blockDim.x + threadIdx.x;
    if (e < EE) {
        int d = ei_at(ei, (size_t)EE + e);
        atomicAdd(&g_counts[d], 1);
    }
}

__global__ void reduce_kernel() {
    int b = blockIdx.x;
    int v = g_counts[b * 256 + threadIdx.x];
    #pragma unroll
    for (int o = 16; o; o >>= 1) v += __shfl_down_sync(0xffffffffu, v, o);
    __shared__ int ws[8];
    if ((threadIdx.x & 31) == 0) ws[threadIdx.x >> 5] = v;
    __syncthreads();
    if (threadIdx.x == 0) {
        int s = 0;
        #pragma unroll
        for (int i = 0; i < 8; i++) s += ws[i];
        g_bsum[b] = s;
    }
}

__global__ void scanpart_kernel() {
    int t = threadIdx.x;
    int v = (t < NN / 256) ? g_bsum[t] : 0;
    int lane = t & 31, w = t >> 5;
    int x = v;
    #pragma unroll
    for (int o = 1; o < 32; o <<= 1) {
        int y = __shfl_up_sync(0xffffffffu, x, o);
        if (lane >= o) x += y;
    }
    __shared__ int ws[8], wso[8];
    if (lane == 31) ws[w] = x;
    __syncthreads();
    if (t < 8) {
        int s = 0;
        for (int i = 0; i < t; i++) s += ws[i];
        wso[t] = s;
    }
    __syncthreads();
    int incl = x + wso[w];
    if (t < NN / 256) g_boff[t] = incl - v;
    if (t == 255) g_offsets[NN] = incl;
}

__global__ void blockscan_kernel() {
    int b = blockIdx.x, t = threadIdx.x, i = b * 256 + t;
    int c = g_counts[i];
    int lane = t & 31, w = t >> 5;
    int x = c;
    #pragma unroll
    for (int o = 1; o < 32; o <<= 1) {
        int y = __shfl_up_sync(0xffffffffu, x, o);
        if (lane >= o) x += y;
    }
    __shared__ int ws[8], wso[8];
    if (lane == 31) ws[w] = x;
    __syncthreads();
    if (t < 8) {
        int s = 0;
        for (int j = 0; j < t; j++) s += ws[j];
        wso[t] = s;
    }
    __syncthreads();
    g_offsets[i] = x - c + wso[w] + g_boff[b];
    g_dinv[i] = rsqrtf((float)(c + 1));
}

// scatter dst-sorted edge records {src, dinv[d]*dinv[s]} (needs g_dinv ready)
__global__ void scatter_kernel(const void* __restrict__ ei) {
    int e = blockIdx.x * blockDim.x + threadIdx.x;
    if (e < EE) {
        int d = ei_at(ei, (size_t)EE + e);
        int s = ei_at(ei, (size_t)e);
        int pos = g_offsets[d] + atomicAdd(&g_fill[d], 1);
        float w = g_dinv[d] * g_dinv[s];
        g_edge[pos] = make_int2(s, __float_as_int(w));
    }
}

// -------------------- x -> fp16 --------------------
__global__ void xconv_kernel(const float* __restrict__ x) {
    int i = blockIdx.x * blockDim.x + threadIdx.x;  // over NN*F_IN/2
    if (i < NN * F_IN / 2) {
        float2 v = ((const float2*)x)[i];
        ((__half2*)g_hf)[i] = __floats2half2_rn(v.x, v.y);
    }
}

// -------------------- weight split: Whi/Wlo[k][n] (layout preserved) ---------
template <int K, int NOUT>
__global__ void splitw_kernel(const float* __restrict__ W) {
    int i = blockIdx.x * blockDim.x + threadIdx.x;
    if (i >= K * NOUT) return;
    float v = W[i];
    __nv_bfloat16 h = __float2bfloat16(v);
    g_wtH[i] = h;
    g_wtL[i] = __float2bfloat16(v - __bfloat162float(h));
}

// -------------------- agg1: fp16 x (H=128) -> split bf16 output --------------
__global__ void agg1_kernel() {
    int gw = (blockIdx.x * blockDim.x + threadIdx.x) >> 5;
    int lane = threadIdx.x & 31;
    if (gw >= NN) return;
    const int n = gw;
    const float dd = g_dinv[n];
    const float w0 = dd * dd;

    float acc[4];
    {
        uint2 hv = ((const uint2*)(g_hf + (size_t)n * F_IN))[lane];
        float2 f0 = h2f2(hv.x), f1 = h2f2(hv.y);
        acc[0] = w0 * f0.x; acc[1] = w0 * f0.y;
        acc[2] = w0 * f1.x; acc[3] = w0 * f1.y;
    }

    const int e0 = g_offsets[n], e1 = g_offsets[n + 1];
    for (int e = e0; e < e1; e++) {
        int2 ew = g_edge[e];
        float w = __int_as_float(ew.y);
        uint2 hv = ((const uint2*)(g_hf + (size_t)ew.x * F_IN))[lane];
        float2 f0 = h2f2(hv.x), f1 = h2f2(hv.y);
        acc[0] += w * f0.x; acc[1] += w * f0.y;
        acc[2] += w * f1.x; acc[3] += w * f1.y;
    }

    uint32_t l0, l1;
    uint32_t h0 = pack_split(acc[0], acc[1], l0);
    uint32_t h1 = pack_split(acc[2], acc[3], l1);
    ((uint2*)(g_ahi + (size_t)n * F_IN))[lane] = make_uint2(h0, h1);
    ((uint2*)(g_alo + (size_t)n * F_IN))[lane] = make_uint2(l0, l1);
}

// -------------------- agg23: fp16 input (H=256) -> split bf16 output ---------
__global__ void agg23_kernel() {
    int gw = (blockIdx.x * blockDim.x + threadIdx.x) >> 5;
    int lane = threadIdx.x & 31;
    if (gw >= NN) return;
    const int n = gw;
    const float dd = g_dinv[n];
    const float w0 = dd * dd;

    float acc[8];
    {
        uint4 hv = ((const uint4*)(g_hf + (size_t)n * 256))[lane];
        float2 f0 = h2f2(hv.x), f1 = h2f2(hv.y), f2 = h2f2(hv.z), f3 = h2f2(hv.w);
        acc[0] = w0 * f0.x; acc[1] = w0 * f0.y; acc[2] = w0 * f1.x; acc[3] = w0 * f1.y;
        acc[4] = w0 * f2.x; acc[5] = w0 * f2.y; acc[6] = w0 * f3.x; acc[7] = w0 * f3.y;
    }

    const int e0 = g_offsets[n], e1 = g_offsets[n + 1];
    for (int e = e0; e < e1; e++) {
        int2 ew = g_edge[e];
        float w = __int_as_float(ew.y);
        uint4 hv = ((const uint4*)(g_hf + (size_t)ew.x * 256))[lane];
        float2 f0 = h2f2(hv.x), f1 = h2f2(hv.y), f2 = h2f2(hv.z), f3 = h2f2(hv.w);
        acc[0] += w * f0.x; acc[1] += w * f0.y; acc[2] += w * f1.x; acc[3] += w * f1.y;
        acc[4] += w * f2.x; acc[5] += w * f2.y; acc[6] += w * f3.x; acc[7] += w * f3.y;
    }

    uint4 ho, lo;
    ho.x = pack_split(acc[0], acc[1], lo.x);
    ho.y = pack_split(acc[2], acc[3], lo.y);
    ho.z = pack_split(acc[4], acc[5], lo.z);
    ho.w = pack_split(acc[6], acc[7], lo.w);
    ((uint4*)(g_ahi + (size_t)n * 256))[lane] = ho;
    ((uint4*)(g_alo + (size_t)n * 256))[lane] = lo;
}

// -------------------- GEMM via mma.sync (HMMA), cp.async double-buffered -----
// CTA tile 128x128, 8 warps (4x2), warp tile 32x64, k-chunk 64, 2-stage pipe.
// Epilogue: v = tanh(acc + bias). HALFOUT=1 -> g_hf fp16; else fp32 g_bufA.
#define A_PITCH 144   // 64 bf16 = 128B + 16B pad
#define B_PITCH 272   // 128 bf16 = 256B + 16B pad
#define SM_AH 0
#define SM_AL (128 * A_PITCH)
#define SM_BH (2 * 128 * A_PITCH)
#define SM_BL (2 * 128 * A_PITCH + 64 * B_PITCH)
#define SM_STG (2 * 128 * A_PITCH + 2 * 64 * B_PITCH)
#define SM_TOT (2 * SM_STG)

template <int K, int NB>
__device__ __forceinline__ void gemm_load_chunk(uint32_t sb, int stg, int m0, int n0,
                                                int k0, int t) {
    uint32_t base = sb + stg * SM_STG;
    #pragma unroll
    for (int i = 0; i < 4; i++) {
        int idx = t + i * 256;
        int row = idx >> 3, seg = idx & 7;
        size_t gofs = ((size_t)(m0 + row) * K + k0) * 2 + seg * 16;
        cpa16(base + SM_AH + row * A_PITCH + seg * 16, (const char*)g_ahi + gofs);
        cpa16(base + SM_AL + row * A_PITCH + seg * 16, (const char*)g_alo + gofs);
    }
    #pragma unroll
    for (int i = 0; i < 4; i++) {
        int idx = t + i * 256;
        int row = idx >> 4, seg = idx & 15;
        size_t gofs = ((size_t)(k0 + row) * NB + n0) * 2 + seg * 16;
        cpa16(base + SM_BH + row * B_PITCH + seg * 16, (const char*)g_wtH + gofs);
        cpa16(base + SM_BL + row * B_PITCH + seg * 16, (const char*)g_wtL + gofs);
    }
    CPA_COMMIT();
}

template <int K, int NB, int HALFOUT>
__global__ void __launch_bounds__(256, 1)
gemm_mma(const float* __restrict__ bias) {
    extern __shared__ char sm[];
    const uint32_t sb = smem_u32(sm);
    const int t = threadIdx.x;
    const int warp = t >> 5, lane = t & 31;
    const int wm = warp >> 1, wn = warp & 1;
    const int m0 = blockIdx.y * 128, n0 = blockIdx.x * 128;
    constexpr int NCH = K / 64;

    float c[2][8][4];
    #pragma unroll
    for (int i = 0; i < 2; i++)
        #pragma unroll
        for (int j = 0; j < 8; j++)
            #pragma unroll
            for (int q = 0; q < 4; q++) c[i][j][q] = 0.0f;

    gemm_load_chunk<K, NB>(sb, 0, m0, n0, 0, t);

    for (int ch = 0; ch < NCH; ch++) {
        CPA_WAIT0();
        __syncthreads();
        if (ch + 1 < NCH)
            gemm_load_chunk<K, NB>(sb, (ch + 1) & 1, m0, n0, (ch + 1) * 64, t);

        const char* base = sm + (ch & 1) * SM_STG;
        #pragma unroll
        for (int k16 = 0; k16 < 4; k16++) {
            uint32_t ah[2][4], al[2][4];
            #pragma unroll
            for (int mt = 0; mt < 2; mt++) {
                int row = wm * 32 + mt * 16 + (lane & 15);
                int cb = k16 * 32 + ((lane >> 4) << 4);
                LDSM_X4(ah[mt], smem_u32(base + SM_AH + row * A_PITCH + cb));
                LDSM_X4(al[mt], smem_u32(base + SM_AL + row * A_PITCH + cb));
            }
            uint32_t bh[4][4], bl[4][4];
            #pragma unroll
            for (int np = 0; np < 4; np++) {
                int krow = k16 * 16 + (lane & 7) + (lane & 8);
                int cb = wn * 128 + np * 32 + ((lane >> 4) << 4);
                LDSM_X4T(bh[np], smem_u32(base + SM_BH + krow * B_PITCH + cb));
                LDSM_X4T(bl[np], smem_u32(base + SM_BL + krow * B_PITCH + cb));
            }
            #pragma unroll
            for (int mt = 0; mt < 2; mt++) {
                #pragma unroll
                for (int np = 0; np < 4; np++) {
                    mma16816(c[mt][np * 2],     ah[mt], bh[np][0], bh[np][1]);
                    mma16816(c[mt][np * 2],     al[mt], bh[np][0], bh[np][1]);
                    mma16816(c[mt][np * 2],     ah[mt], bl[np][0], bl[np][1]);
                    mma16816(c[mt][np * 2 + 1], ah[mt], bh[np][2], bh[np][3]);
                    mma16816(c[mt][np * 2 + 1], al[mt], bh[np][2], bh[np][3]);
                    mma16816(c[mt][np * 2 + 1], ah[mt], bl[np][2], bl[np][3]);
                }
            }
        }
        __syncthreads();
    }

    // epilogue: tanh(acc + bias) -> fp16 (for gather) or fp32 (for FC)
    const int g = lane >> 2, tq = lane & 3;
    #pragma unroll
    for (int mt = 0; mt < 2; mt++) {
        int row = m0 + wm * 32 + mt * 16 + g;
        #pragma unroll
        for (int n8 = 0; n8 < 8; n8++) {
            int col = n0 + wn * 64 + n8 * 8 + 2 * tq;
            float b0 = __ldg(bias + col), b1 = __ldg(bias + col + 1);
            float v0 = tanhf(c[mt][n8][0] + b0);
            float v1 = tanhf(c[mt][n8][1] + b1);
            float v2 = tanhf(c[mt][n8][2] + b0);
            float v3 = tanhf(c[mt][n8][3] + b1);
            if (HALFOUT) {
                *(__half2*)(g_hf + (size_t)row * NB + col) = __floats2half2_rn(v0, v1);
                *(__half2*)(g_hf + (size_t)(row + 8) * NB + col) = __floats2half2_rn(v2, v3);
            } else {
                *(float2*)(g_bufA + (size_t)row * NB + col) = make_float2(v0, v1);
                *(float2*)(g_bufA + (size_t)(row + 8) * NB + col) = make_float2(v2, v3);
            }
        }
    }
}

// -------------------- final FC: out[64,64] = h3.reshape(64,128000) @ Wfc + bfc
__global__ void fc_init(const float* __restrict__ bfc, float* __restrict__ out) {
    int i = blockIdx.x * blockDim.x + threadIdx.x;
    if (i < NG * OUTD) out[i] = bfc[i & 63];
}

#define FC_KCH 1024
__global__ void fc_kernel(const float* __restrict__ Wfc,
                          float* __restrict__ out) {
    const float* __restrict__ h3 = g_bufA;
    __shared__ float Ws[16][64];
    __shared__ float Hs[64][17];
    const int t = threadIdx.x;
    const int tg = t & 15;
    const int to = t >> 4;
    float acc[4][4];
    #pragma unroll
    for (int i = 0; i < 4; i++)
        #pragma unroll
        for (int j = 0; j < 4; j++) acc[i][j] = 0.0f;

    const int kbase = blockIdx.x * FC_KCH;
    for (int kk0 = 0; kk0 < FC_KCH; kk0 += 16) {
        const int k0 = kbase + kk0;
        #pragma unroll
        for (int rr = 0; rr < 4; rr++) {
            int idx = t + rr * 256;
            int kr = idx >> 6, nn = idx & 63;
            Ws[kr][nn] = Wfc[(size_t)(k0 + kr) * OUTD + nn];
        }
        #pragma unroll
        for (int rr = 0; rr < 4; rr++) {
            int idx = t + rr * 256;
            int g = idx >> 4, kk = idx & 15;
            Hs[g][kk] = h3[(size_t)g * 128000 + k0 + kk];
        }
        __syncthreads();
        #pragma unroll
        for (int kk = 0; kk < 16; kk++) {
            float hv[4], wv[4];
            #pragma unroll
            for (int i = 0; i < 4; i++) hv[i] = Hs[4 * tg + i][kk];
            #pragma unroll
            for (int j = 0; j < 4; j++) wv[j] = Ws[kk][4 * to + j];
            #pragma unroll
            for (int i = 0; i < 4; i++)
                #pragma unroll
                for (int j = 0; j < 4; j++) acc[i][j] += hv[i] * wv[j];
        }
        __syncthreads();
    }
    #pragma unroll
    for (int i = 0; i < 4; i++)
        #pragma unroll
        for (int j = 0; j < 4; j++)
            atomicAdd(&out[(4 * tg + i) * OUTD + 4 * to + j], acc[i][j]);
}

// -------------------- launch --------------------
extern "C" void kernel_launch(void* const* d_in, const int* in_sizes, int n_in,
                              void* d_out, int out_size) {
    const float* x   = (const float*)d_in[0];
    const void*  ei  = d_in[1];
    const float* W1  = (const float*)d_in[3];
    const float* b1  = (const float*)d_in[4];
    const float* W2  = (const float*)d_in[5];
    const float* b2  = (const float*)d_in[6];
    const float* W3  = (const float*)d_in[7];
    const float* b3  = (const float*)d_in[8];
    const float* Wfc = (const float*)d_in[9];
    const float* bfc = (const float*)d_in[10];
    float* out = (float*)d_out;

    cudaFuncSetAttribute(gemm_mma<F_IN, H1, 1>, cudaFuncAttributeMaxDynamicSharedMemorySize, SM_TOT);
    cudaFuncSetAttribute(gemm_mma<H1, H2, 1>,   cudaFuncAttributeMaxDynamicSharedMemorySize, SM_TOT);
    cudaFuncSetAttribute(gemm_mma<H2, H3, 0>,   cudaFuncAttributeMaxDynamicSharedMemorySize, SM_TOT);

    // preprocessing
    detect_kernel<<<1, 1>>>(ei);
    zero_kernel<<<(NN + 255) / 256, 256>>>();
    hist_kernel<<<EE / 256, 256>>>(ei);
    reduce_kernel<<<NN / 256, 256>>>();
    scanpart_kernel<<<1, 256>>>();
    blockscan_kernel<<<NN / 256, 256>>>();
    scatter_kernel<<<EE / 256, 256>>>(ei);
    xconv_kernel<<<(NN * F_IN / 2 + 255) / 256, 256>>>(x);

    const int aggBlocks = (NN * 32) / 256;

    // layer 1: agg-first (Â x, fp16 gather) then GEMM(128->256), tanh -> fp16
    splitw_kernel<F_IN, H1><<<(F_IN * H1 + 255) / 256, 256>>>(W1);
    agg1_kernel<<<aggBlocks, 256>>>();
    gemm_mma<F_IN, H1, 1><<<dim3(H1 / 128, NN / 128), 256, SM_TOT>>>(b1);

    // layer 2: agg (fp16 gather, 256) then GEMM(256->256), tanh -> fp16
    splitw_kernel<H1, H2><<<(H1 * H2 + 255) / 256, 256>>>(W2);
    agg23_kernel<<<aggBlocks, 256>>>();
    gemm_mma<H1, H2, 1><<<dim3(H2 / 128, NN / 128), 256, SM_TOT>>>(b2);

    // layer 3: agg then GEMM(256->128), tanh -> fp32 for FC
    splitw_kernel<H2, H3><<<(H2 * H3 + 255) / 256, 256>>>(W3);
    agg23_kernel<<<aggBlocks, 256>>>();
    gemm_mma<H2, H3, 0><<<dim3(H3 / 128, NN / 128), 256, SM_TOT>>>(b3);

    // final FC with split-K atomics
    fc_init<<<(NG * OUTD + 255) / 256, 256>>>(bfc, out);
    fc_kernel<<<128000 / FC_KCH, 256>>>(Wfc, out);
}

// round 11
// speedup vs baseline: 1.3923x; 1.1391x over previous
#include <cuda_runtime.h>
#include <cuda_bf16.h>
#include <cuda_fp16.h>
#include <cstdint>
#include <cstddef>

// Problem constants (fixed by the dataset)
#define NN 64000
#define EE 1048576
#define NG 64
#define NBN 1000
#define F_IN 128
#define H1 256
#define H2 256
#define H3 128
#define OUTD 64

// -------------------- scratch (device globals; no allocs) --------------------
__device__ __align__(16) float g_bufA[(size_t)NN * 256];   // fp32 h3 for FC
__device__ __align__(16) __half g_af[(size_t)NN * 256];    // fp16 aggregated (GEMM A)
__device__ __align__(16) __half g_hf[(size_t)NN * 256];    // fp16 activations (gather src)
__device__ __align__(16) __half g_wtH[256 * 256];          // W hi fp16, [k][n]
__device__ __align__(16) __half g_wtL[256 * 256];          // W lo fp16 residual, [k][n]
__device__ int2  g_edge[EE];                               // {src, w = dinv[d]*dinv[s]}
__device__ int   g_counts[NN];
__device__ int   g_offsets[NN + 1];
__device__ int   g_fill[NN];
__device__ float g_dinv[NN];
__device__ int   g_isI64;
__device__ int   g_bsum[256];
__device__ int   g_boff[256];

__device__ __forceinline__ int ei_at(const void* ei, size_t idx) {
    if (g_isI64) return (int)((const long long*)ei)[idx];
    return ((const int*)ei)[idx];
}

// -------------------- PTX helpers (family-generic sm_80+ features only) ------
__device__ __forceinline__ uint32_t smem_u32(const void* p) {
    uint32_t a;
    asm("{ .reg .u64 t; cvta.to.shared.u64 t, %1; cvt.u32.u64 %0, t; }" : "=r"(a) : "l"(p));
    return a;
}
__device__ __forceinline__ void cpa16(uint32_t s, const void* g) {
    asm volatile("cp.async.cg.shared.global [%0], [%1], 16;" :: "r"(s), "l"(g) : "memory");
}
#define CPA_COMMIT() asm volatile("cp.async.commit_group;" ::: "memory")
#define CPA_WAIT0()  asm volatile("cp.async.wait_group 0;" ::: "memory")

#define LDSM_X4(r, a)                                                              \
    asm volatile("ldmatrix.sync.aligned.m8n8.x4.shared.b16 {%0,%1,%2,%3}, [%4];"   \
                 : "=r"((r)[0]), "=r"((r)[1]), "=r"((r)[2]), "=r"((r)[3]) : "r"(a))
#define LDSM_X4T(r, a)                                                                  \
    asm volatile("ldmatrix.sync.aligned.m8n8.x4.trans.shared.b16 {%0,%1,%2,%3}, [%4];"  \
                 : "=r"((r)[0]), "=r"((r)[1]), "=r"((r)[2]), "=r"((r)[3]) : "r"(a))

__device__ __forceinline__ void mma16816h(float* c, const uint32_t* a,
                                          uint32_t b0, uint32_t b1) {
    asm volatile(
        "mma.sync.aligned.m16n8k16.row.col.f32.f16.f16.f32 "
        "{%0,%1,%2,%3}, {%4,%5,%6,%7}, {%8,%9}, {%0,%1,%2,%3};"
        : "+f"(c[0]), "+f"(c[1]), "+f"(c[2]), "+f"(c[3])
        : "r"(a[0]), "r"(a[1]), "r"(a[2]), "r"(a[3]), "r"(b0), "r"(b1));
}

__device__ __forceinline__ float2 h2f2(uint32_t u) {
    return __half22float2(*(__half2*)&u);
}

// -------------------- dtype detection --------------------
__global__ void detect_kernel(const void* ei) {
    const unsigned int* w = (const unsigned int*)ei;
    int is64 = 1;
    #pragma unroll
    for (int i = 0; i < 32; i++)
        if (w[2 * i + 1] != 0u) is64 = 0;
    g_isI64 = is64;
}

// -------------------- preprocessing --------------------
__global__ void zero_kernel() {
    int i = blockIdx.x * blockDim.x + threadIdx.x;
    if (i < NN) { g_fill[i] = 0; g_counts[i] = 0; }
}

__global__ void hist_kernel(const void* __restrict__ ei) {
    int e = blockIdx.x * blockDim.x + threadIdx.x;
    if (e < EE) {
        int d = ei_at(ei, (size_t)EE + e);
        atomicAdd(&g_counts[d], 1);
    }
}

__global__ void reduce_kernel() {
    int b = blockIdx.x;
    int v = g_counts[b * 256 + threadIdx.x];
    #pragma unroll
    for (int o = 16; o; o >>= 1) v += __shfl_down_sync(0xffffffffu, v, o);
    __shared__ int ws[8];
    if ((threadIdx.x & 31) == 0) ws[threadIdx.x >> 5] = v;
    __syncthreads();
    if (threadIdx.x == 0) {
        int s = 0;
        #pragma unroll
        for (int i = 0; i < 8; i++) s += ws[i];
        g_bsum[b] = s;
    }
}

__global__ void scanpart_kernel() {
    int t = threadIdx.x;
    int v = (t < NN / 256) ? g_bsum[t] : 0;
    int lane = t & 31, w = t >> 5;
    int x = v;
    #pragma unroll
    for (int o = 1; o < 32; o <<= 1) {
        int y = __shfl_up_sync(0xffffffffu, x, o);
        if (lane >= o) x += y;
    }
    __shared__ int ws[8], wso[8];
    if (lane == 31) ws[w] = x;
    __syncthreads();
    if (t < 8) {
        int s = 0;
        for (int i = 0; i < t; i++) s += ws[i];
        wso[t] = s;
    }
    __syncthreads();
    int incl = x + wso[w];
    if (t < NN / 256) g_boff[t] = incl - v;
    if (t == 255) g_offsets[NN] = incl;
}

__global__ void blockscan_kernel() {
    int b = blockIdx.x, t = threadIdx.x, i = b * 256 + t;
    int c = g_counts[i];
    int lane = t & 31, w = t >> 5;
    int x = c;
    #pragma unroll
    for (int o = 1; o < 32; o <<= 1) {
        int y = __shfl_up_sync(0xffffffffu, x, o);
        if (lane >= o) x += y;
    }
    __shared__ int ws[8], wso[8];
    if (lane == 31) ws[w] = x;
    __syncthreads();
    if (t < 8) {
        int s = 0;
        for (int j = 0; j < t; j++) s += ws[j];
        wso[t] = s;
    }
    __syncthreads();
    g_offsets[i] = x - c + wso[w] + g_boff[b];
    g_dinv[i] = rsqrtf((float)(c + 1));
}

// scatter dst-sorted edge records {src, dinv[d]*dinv[s]} (needs g_dinv ready)
__global__ void scatter_kernel(const void* __restrict__ ei) {
    int e = blockIdx.x * blockDim.x + threadIdx.x;
    if (e < EE) {
        int d = ei_at(ei, (size_t)EE + e);
        int s = ei_at(ei, (size_t)e);
        int pos = g_offsets[d] + atomicAdd(&g_fill[d], 1);
        float w = g_dinv[d] * g_dinv[s];
        g_edge[pos] = make_int2(s, __float_as_int(w));
    }
}

// -------------------- x -> fp16 --------------------
__global__ void xconv_kernel(const float* __restrict__ x) {
    int i = blockIdx.x * blockDim.x + threadIdx.x;  // over NN*F_IN/2
    if (i < NN * F_IN / 2) {
        float2 v = ((const float2*)x)[i];
        ((__half2*)g_hf)[i] = __floats2half2_rn(v.x, v.y);
    }
}

// -------------------- weight split: Whi/Wlo fp16 [k][n] ----------------------
template <int K, int NOUT>
__global__ void splitw_kernel(const float* __restrict__ W) {
    int i = blockIdx.x * blockDim.x + threadIdx.x;
    if (i >= K * NOUT) return;
    float v = W[i];
    __half h = __float2half_rn(v);
    g_wtH[i] = h;
    g_wtL[i] = __float2half_rn(v - __half2float(h));
}

// -------------------- agg1: fp16 x (H=128) -> fp16 output --------------------
__global__ void agg1_kernel() {
    int gw = (blockIdx.x * blockDim.x + threadIdx.x) >> 5;
    int lane = threadIdx.x & 31;
    if (gw >= NN) return;
    const int n = gw;
    const float dd = g_dinv[n];
    const float w0 = dd * dd;

    float acc[4];
    {
        uint2 hv = ((const uint2*)(g_hf + (size_t)n * F_IN))[lane];
        float2 f0 = h2f2(hv.x), f1 = h2f2(hv.y);
        acc[0] = w0 * f0.x; acc[1] = w0 * f0.y;
        acc[2] = w0 * f1.x; acc[3] = w0 * f1.y;
    }

    const int e0 = g_offsets[n], e1 = g_offsets[n + 1];
    for (int e = e0; e < e1; e++) {
        int2 ew = g_edge[e];
        float w = __int_as_float(ew.y);
        uint2 hv = ((const uint2*)(g_hf + (size_t)ew.x * F_IN))[lane];
        float2 f0 = h2f2(hv.x), f1 = h2f2(hv.y);
        acc[0] += w * f0.x; acc[1] += w * f0.y;
        acc[2] += w * f1.x; acc[3] += w * f1.y;
    }

    __half2 o0 = __floats2half2_rn(acc[0], acc[1]);
    __half2 o1 = __floats2half2_rn(acc[2], acc[3]);
    ((uint2*)(g_af + (size_t)n * F_IN))[lane] =
        make_uint2(*(uint32_t*)&o0, *(uint32_t*)&o1);
}

// -------------------- agg23: fp16 input (H=256) -> fp16 output ---------------
__global__ void agg23_kernel() {
    int gw = (blockIdx.x * blockDim.x + threadIdx.x) >> 5;
    int lane = threadIdx.x & 31;
    if (gw >= NN) return;
    const int n = gw;
    const float dd = g_dinv[n];
    const float w0 = dd * dd;

    float acc[8];
    {
        uint4 hv = ((const uint4*)(g_hf + (size_t)n * 256))[lane];
        float2 f0 = h2f2(hv.x), f1 = h2f2(hv.y), f2 = h2f2(hv.z), f3 = h2f2(hv.w);
        acc[0] = w0 * f0.x; acc[1] = w0 * f0.y; acc[2] = w0 * f1.x; acc[3] = w0 * f1.y;
        acc[4] = w0 * f2.x; acc[5] = w0 * f2.y; acc[6] = w0 * f3.x; acc[7] = w0 * f3.y;
    }

    const int e0 = g_offsets[n], e1 = g_offsets[n + 1];
    for (int e = e0; e < e1; e++) {
        int2 ew = g_edge[e];
        float w = __int_as_float(ew.y);
        uint4 hv = ((const uint4*)(g_hf + (size_t)ew.x * 256))[lane];
        float2 f0 = h2f2(hv.x), f1 = h2f2(hv.y), f2 = h2f2(hv.z), f3 = h2f2(hv.w);
        acc[0] += w * f0.x; acc[1] += w * f0.y; acc[2] += w * f1.x; acc[3] += w * f1.y;
        acc[4] += w * f2.x; acc[5] += w * f2.y; acc[6] += w * f3.x; acc[7] += w * f3.y;
    }

    __half2 o0 = __floats2half2_rn(acc[0], acc[1]);
    __half2 o1 = __floats2half2_rn(acc[2], acc[3]);
    __half2 o2 = __floats2half2_rn(acc[4], acc[5]);
    __half2 o3 = __floats2half2_rn(acc[6], acc[7]);
    uint4 ov;
    ov.x = *(uint32_t*)&o0; ov.y = *(uint32_t*)&o1;
    ov.z = *(uint32_t*)&o2; ov.w = *(uint32_t*)&o3;
    ((uint4*)(g_af + (size_t)n * 256))[lane] = ov;
}

// -------------------- GEMM via mma.sync fp16, cp.async double-buffered -------
// CTA tile 128x128, 8 warps (4x2), warp tile 32x64, k-chunk 64, 2-stage pipe.
// A = single fp16, W = fp16 hi + fp16 residual -> 2 MMA terms, fp32 accum.
// Epilogue: v = tanh(acc + bias). HALFOUT=1 -> g_hf fp16; else fp32 g_bufA.
#define A_PITCH 144   // 64 fp16 = 128B + 16B pad
#define B_PITCH 272   // 128 fp16 = 256B + 16B pad
#define SM_A  0
#define SM_BH (128 * A_PITCH)
#define SM_BL (128 * A_PITCH + 64 * B_PITCH)
#define SM_STG (128 * A_PITCH + 2 * 64 * B_PITCH)
#define SM_TOT (2 * SM_STG)

template <int K, int NB>
__device__ __forceinline__ void gemm_load_chunk(uint32_t sb, int stg, int m0, int n0,
                                                int k0, int t) {
    uint32_t base = sb + stg * SM_STG;
    #pragma unroll
    for (int i = 0; i < 4; i++) {
        int idx = t + i * 256;
        int row = idx >> 3, seg = idx & 7;
        size_t gofs = ((size_t)(m0 + row) * K + k0) * 2 + seg * 16;
        cpa16(base + SM_A + row * A_PITCH + seg * 16, (const char*)g_af + gofs);
    }
    #pragma unroll
    for (int i = 0; i < 4; i++) {
        int idx = t + i * 256;
        int row = idx >> 4, seg = idx & 15;
        size_t gofs = ((size_t)(k0 + row) * NB + n0) * 2 + seg * 16;
        cpa16(base + SM_BH + row * B_PITCH + seg * 16, (const char*)g_wtH + gofs);
        cpa16(base + SM_BL + row * B_PITCH + seg * 16, (const char*)g_wtL + gofs);
    }
    CPA_COMMIT();
}

template <int K, int NB, int HALFOUT>
__global__ void __launch_bounds__(256, 1)
gemm_mma(const float* __restrict__ bias) {
    extern __shared__ char sm[];
    const uint32_t sb = smem_u32(sm);
    const int t = threadIdx.x;
    const int warp = t >> 5, lane = t & 31;
    const int wm = warp >> 1, wn = warp & 1;
    const int m0 = blockIdx.y * 128, n0 = blockIdx.x * 128;
    constexpr int NCH = K / 64;

    float c[2][8][4];
    #pragma unroll
    for (int i = 0; i < 2; i++)
        #pragma unroll
        for (int j = 0; j < 8; j++)
            #pragma unroll
            for (int q = 0; q < 4; q++) c[i][j][q] = 0.0f;

    gemm_load_chunk<K, NB>(sb, 0, m0, n0, 0, t);

    for (int ch = 0; ch < NCH; ch++) {
        CPA_WAIT0();
        __syncthreads();
        if (ch + 1 < NCH)
            gemm_load_chunk<K, NB>(sb, (ch + 1) & 1, m0, n0, (ch + 1) * 64, t);

        const char* base = sm + (ch & 1) * SM_STG;
        #pragma unroll
        for (int k16 = 0; k16 < 4; k16++) {
            uint32_t aa[2][4];
            #pragma unroll
            for (int mt = 0; mt < 2; mt++) {
                int row = wm * 32 + mt * 16 + (lane & 15);
                int cb = k16 * 32 + ((lane >> 4) << 4);
                LDSM_X4(aa[mt], smem_u32(base + SM_A + row * A_PITCH + cb));
            }
            uint32_t bh[4][4], bl[4][4];
            #pragma unroll
            for (int np = 0; np < 4; np++) {
                int krow = k16 * 16 + (lane & 7) + (lane & 8);
                int cb = wn * 128 + np * 32 + ((lane >> 4) << 4);
                LDSM_X4T(bh[np], smem_u32(base + SM_BH + krow * B_PITCH + cb));
                LDSM_X4T(bl[np], smem_u32(base + SM_BL + krow * B_PITCH + cb));
            }
            #pragma unroll
            for (int mt = 0; mt < 2; mt++) {
                #pragma unroll
                for (int np = 0; np < 4; np++) {
                    mma16816h(c[mt][np * 2],     aa[mt], bh[np][0], bh[np][1]);
                    mma16816h(c[mt][np * 2],     aa[mt], bl[np][0], bl[np][1]);
                    mma16816h(c[mt][np * 2 + 1], aa[mt], bh[np][2], bh[np][3]);
                    mma16816h(c[mt][np * 2 + 1], aa[mt], bl[np][2], bl[np][3]);
                }
            }
        }
        __syncthreads();
    }

    // epilogue: tanh(acc + bias) -> fp16 (for gather) or fp32 (for FC)
    const int g = lane >> 2, tq = lane & 3;
    #pragma unroll
    for (int mt = 0; mt < 2; mt++) {
        int row = m0 + wm * 32 + mt * 16 + g;
        #pragma unroll
        for (int n8 = 0; n8 < 8; n8++) {
            int col = n0 + wn * 64 + n8 * 8 + 2 * tq;
            float b0 = __ldg(bias + col), b1 = __ldg(bias + col + 1);
            float v0 = tanhf(c[mt][n8][0] + b0);
            float v1 = tanhf(c[mt][n8][1] + b1);
            float v2 = tanhf(c[mt][n8][2] + b0);
            float v3 = tanhf(c[mt][n8][3] + b1);
            if (HALFOUT) {
                *(__half2*)(g_hf + (size_t)row * NB + col) = __floats2half2_rn(v0, v1);
                *(__half2*)(g_hf + (size_t)(row + 8) * NB + col) = __floats2half2_rn(v2, v3);
            } else {
                *(float2*)(g_bufA + (size_t)row * NB + col) = make_float2(v0, v1);
                *(float2*)(g_bufA + (size_t)(row + 8) * NB + col) = make_float2(v2, v3);
            }
        }
    }
}

// -------------------- final FC: out[64,64] = h3.reshape(64,128000) @ Wfc + bfc
__global__ void fc_init(const float* __restrict__ bfc, float* __restrict__ out) {
    int i = blockIdx.x * blockDim.x + threadIdx.x;
    if (i < NG * OUTD) out[i] = bfc[i & 63];
}

#define FC_KCH 1024
__global__ void fc_kernel(const float* __restrict__ Wfc,
                          float* __restrict__ out) {
    const float* __restrict__ h3 = g_bufA;
    __shared__ float Ws[16][64];
    __shared__ float Hs[64][17];
    const int t = threadIdx.x;
    const int tg = t & 15;
    const int to = t >> 4;
    float acc[4][4];
    #pragma unroll
    for (int i = 0; i < 4; i++)
        #pragma unroll
        for (int j = 0; j < 4; j++) acc[i][j] = 0.0f;

    const int kbase = blockIdx.x * FC_KCH;
    for (int kk0 = 0; kk0 < FC_KCH; kk0 += 16) {
        const int k0 = kbase + kk0;
        #pragma unroll
        for (int rr = 0; rr < 4; rr++) {
            int idx = t + rr * 256;
            int kr = idx >> 6, nn = idx & 63;
            Ws[kr][nn] = Wfc[(size_t)(k0 + kr) * OUTD + nn];
        }
        #pragma unroll
        for (int rr = 0; rr < 4; rr++) {
            int idx = t + rr * 256;
            int g = idx >> 4, kk = idx & 15;
            Hs[g][kk] = h3[(size_t)g * 128000 + k0 + kk];
        }
        __syncthreads();
        #pragma unroll
        for (int kk = 0; kk < 16; kk++) {
            float hv[4], wv[4];
            #pragma unroll
            for (int i = 0; i < 4; i++) hv[i] = Hs[4 * tg + i][kk];
            #pragma unroll
            for (int j = 0; j < 4; j++) wv[j] = Ws[kk][4 * to + j];
            #pragma unroll
            for (int i = 0; i < 4; i++)
                #pragma unroll
                for (int j = 0; j < 4; j++) acc[i][j] += hv[i] * wv[j];
        }
        __syncthreads();
    }
    #pragma unroll
    for (int i = 0; i < 4; i++)
        #pragma unroll
        for (int j = 0; j < 4; j++)
            atomicAdd(&out[(4 * tg + i) * OUTD + 4 * to + j], acc[i][j]);
}

// -------------------- launch --------------------
extern "C" void kernel_launch(void* const* d_in, const int* in_sizes, int n_in,
                              void* d_out, int out_size) {
    const float* x   = (const float*)d_in[0];
    const void*  ei  = d_in[1];
    const float* W1  = (const float*)d_in[3];
    const float* b1  = (const float*)d_in[4];
    const float* W2  = (const float*)d_in[5];
    const float* b2  = (const float*)d_in[6];
    const float* W3  = (const float*)d_in[7];
    const float* b3  = (const float*)d_in[8];
    const float* Wfc = (const float*)d_in[9];
    const float* bfc = (const float*)d_in[10];
    float* out = (float*)d_out;

    cudaFuncSetAttribute(gemm_mma<F_IN, H1, 1>, cudaFuncAttributeMaxDynamicSharedMemorySize, SM_TOT);
    cudaFuncSetAttribute(gemm_mma<H1, H2, 1>,   cudaFuncAttributeMaxDynamicSharedMemorySize, SM_TOT);
    cudaFuncSetAttribute(gemm_mma<H2, H3, 0>,   cudaFuncAttributeMaxDynamicSharedMemorySize, SM_TOT);

    // preprocessing
    detect_kernel<<<1, 1>>>(ei);
    zero_kernel<<<(NN + 255) / 256, 256>>>();
    hist_kernel<<<EE / 256, 256>>>(ei);
    reduce_kernel<<<NN / 256, 256>>>();
    scanpart_kernel<<<1, 256>>>();
    blockscan_kernel<<<NN / 256, 256>>>();
    scatter_kernel<<<EE / 256, 256>>>(ei);
    xconv_kernel<<<(NN * F_IN / 2 + 255) / 256, 256>>>(x);

    const int aggBlocks = (NN * 32) / 256;

    // layer 1: agg-first (Â x, fp16 gather) then GEMM(128->256), tanh -> fp16
    splitw_kernel<F_IN, H1><<<(F_IN * H1 + 255) / 256, 256>>>(W1);
    agg1_kernel<<<aggBlocks, 256>>>();
    gemm_mma<F_IN, H1, 1><<<dim3(H1 / 128, NN / 128), 256, SM_TOT>>>(b1);

    // layer 2: agg (fp16 gather, 256) then GEMM(256->256), tanh -> fp16
    splitw_kernel<H1, H2><<<(H1 * H2 + 255) / 256, 256>>>(W2);
    agg23_kernel<<<aggBlocks, 256>>>();
    gemm_mma<H1, H2, 1><<<dim3(H2 / 128, NN / 128), 256, SM_TOT>>>(b2);

    // layer 3: agg then GEMM(256->128), tanh -> fp32 for FC
    splitw_kernel<H2, H3><<<(H2 * H3 + 255) / 256, 256>>>(W3);
    agg23_kernel<<<aggBlocks, 256>>>();
    gemm_mma<H2, H3, 0><<<dim3(H3 / 128, NN / 128), 256, SM_TOT>>>(b3);

    // final FC with split-K atomics
    fc_init<<<(NG * OUTD + 255) / 256, 256>>>(bfc, out);
    fc_kernel<<<128000 / FC_KCH, 256>>>(Wfc, out);
}

// round 12
// speedup vs baseline: 1.5218x; 1.0930x over previous
#include <cuda_runtime.h>
#include <cuda_bf16.h>
#include <cuda_fp16.h>
#include <cstdint>
#include <cstddef>

// Problem constants (fixed by the dataset)
#define NN 64000
#define EE 1048576
#define NG 64
#define NBN 1000
#define F_IN 128
#define H1 256
#define H2 256
#define H3 128
#define OUTD 64

// -------------------- scratch (device globals; no allocs) --------------------
__device__ __align__(16) __half g_af[(size_t)NN * 256];    // fp16 aggregated (GEMM A)
__device__ __align__(16) __half g_hf[(size_t)NN * 256];    // fp16 activations (gather src / h3)
__device__ __align__(16) __half g_w1H[F_IN * H1], g_w1L[F_IN * H1];
__device__ __align__(16) __half g_w2H[H1 * H2],  g_w2L[H1 * H2];
__device__ __align__(16) __half g_w3H[H2 * H3],  g_w3L[H2 * H3];
__device__ int2  g_edge[EE];                               // {src, w = dinv[d]*dinv[s]}
__device__ int   g_counts[NN];
__device__ int   g_offsets[NN + 1];
__device__ int   g_fill[NN];
__device__ float g_dinv[NN];
__device__ int   g_isI64;
__device__ int   g_bsum[256];
__device__ int   g_boff[256];

__device__ __forceinline__ int ei_at(const void* ei, size_t idx) {
    if (g_isI64) return (int)((const long long*)ei)[idx];
    return ((const int*)ei)[idx];
}

// weight-buffer selector (device-side only)
__device__ __forceinline__ const __half* wselH(int s) {
    return s == 1 ? g_w1H : (s == 2 ? g_w2H : g_w3H);
}
__device__ __forceinline__ const __half* wselL(int s) {
    return s == 1 ? g_w1L : (s == 2 ? g_w2L : g_w3L);
}

// -------------------- PTX helpers (family-generic sm_80+ features only) ------
__device__ __forceinline__ uint32_t smem_u32(const void* p) {
    uint32_t a;
    asm("{ .reg .u64 t; cvta.to.shared.u64 t, %1; cvt.u32.u64 %0, t; }" : "=r"(a) : "l"(p));
    return a;
}
__device__ __forceinline__ void cpa16(uint32_t s, const void* g) {
    asm volatile("cp.async.cg.shared.global [%0], [%1], 16;" :: "r"(s), "l"(g) : "memory");
}
#define CPA_COMMIT() asm volatile("cp.async.commit_group;" ::: "memory")
#define CPA_WAIT0()  asm volatile("cp.async.wait_group 0;" ::: "memory")

#define LDSM_X4(r, a)                                                              \
    asm volatile("ldmatrix.sync.aligned.m8n8.x4.shared.b16 {%0,%1,%2,%3}, [%4];"   \
                 : "=r"((r)[0]), "=r"((r)[1]), "=r"((r)[2]), "=r"((r)[3]) : "r"(a))
#define LDSM_X4T(r, a)                                                                  \
    asm volatile("ldmatrix.sync.aligned.m8n8.x4.trans.shared.b16 {%0,%1,%2,%3}, [%4];"  \
                 : "=r"((r)[0]), "=r"((r)[1]), "=r"((r)[2]), "=r"((r)[3]) : "r"(a))

__device__ __forceinline__ void mma16816h(float* c, const uint32_t* a,
                                          uint32_t b0, uint32_t b1) {
    asm volatile(
        "mma.sync.aligned.m16n8k16.row.col.f32.f16.f16.f32 "
        "{%0,%1,%2,%3}, {%4,%5,%6,%7}, {%8,%9}, {%0,%1,%2,%3};"
        : "+f"(c[0]), "+f"(c[1]), "+f"(c[2]), "+f"(c[3])
        : "r"(a[0]), "r"(a[1]), "r"(a[2]), "r"(a[3]), "r"(b0), "r"(b1));
}

__device__ __forceinline__ float2 h2f2(uint32_t u) {
    return __half22float2(*(__half2*)&u);
}

// -------------------- dtype detection --------------------
__global__ void detect_kernel(const void* ei) {
    const unsigned int* w = (const unsigned int*)ei;
    int is64 = 1;
    #pragma unroll
    for (int i = 0; i < 32; i++)
        if (w[2 * i + 1] != 0u) is64 = 0;
    g_isI64 = is64;
}

// -------------------- preprocessing --------------------
__global__ void zero_kernel() {
    int i = blockIdx.x * blockDim.x + threadIdx.x;
    if (i < NN) { g_fill[i] = 0; g_counts[i] = 0; }
}

__global__ void hist_kernel(const void* __restrict__ ei) {
    int e = blockIdx.x * blockDim.x + threadIdx.x;
    if (e < EE) {
        int d = ei_at(ei, (size_t)EE + e);
        atomicAdd(&g_counts[d], 1);
    }
}

__global__ void reduce_kernel() {
    int b = blockIdx.x;
    int v = g_counts[b * 256 + threadIdx.x];
    #pragma unroll
    for (int o = 16; o; o >>= 1) v += __shfl_down_sync(0xffffffffu, v, o);
    __shared__ int ws[8];
    if ((threadIdx.x & 31) == 0) ws[threadIdx.x >> 5] = v;
    __syncthreads();
    if (threadIdx.x == 0) {
        int s = 0;
        #pragma unroll
        for (int i = 0; i < 8; i++) s += ws[i];
        g_bsum[b] = s;
    }
}

__global__ void scanpart_kernel() {
    int t = threadIdx.x;
    int v = (t < NN / 256) ? g_bsum[t] : 0;
    int lane = t & 31, w = t >> 5;
    int x = v;
    #pragma unroll
    for (int o = 1; o < 32; o <<= 1) {
        int y = __shfl_up_sync(0xffffffffu, x, o);
        if (lane >= o) x += y;
    }
    __shared__ int ws[8], wso[8];
    if (lane == 31) ws[w] = x;
    __syncthreads();
    if (t < 8) {
        int s = 0;
        for (int i = 0; i < t; i++) s += ws[i];
        wso[t] = s;
    }
    __syncthreads();
    int incl = x + wso[w];
    if (t < NN / 256) g_boff[t] = incl - v;
    if (t == 255) g_offsets[NN] = incl;
}

__global__ void blockscan_kernel() {
    int b = blockIdx.x, t = threadIdx.x, i = b * 256 + t;
    int c = g_counts[i];
    int lane = t & 31, w = t >> 5;
    int x = c;
    #pragma unroll
    for (int o = 1; o < 32; o <<= 1) {
        int y = __shfl_up_sync(0xffffffffu, x, o);
        if (lane >= o) x += y;
    }
    __shared__ int ws[8], wso[8];
    if (lane == 31) ws[w] = x;
    __syncthreads();
    if (t < 8) {
        int s = 0;
        for (int j = 0; j < t; j++) s += ws[j];
        wso[t] = s;
    }
    __syncthreads();
    g_offsets[i] = x - c + wso[w] + g_boff[b];
    g_dinv[i] = rsqrtf((float)(c + 1));
}

// scatter dst-sorted edge records {src, dinv[d]*dinv[s]} (needs g_dinv ready)
__global__ void scatter_kernel(const void* __restrict__ ei) {
    int e = blockIdx.x * blockDim.x + threadIdx.x;
    if (e < EE) {
        int d = ei_at(ei, (size_t)EE + e);
        int s = ei_at(ei, (size_t)e);
        int pos = g_offsets[d] + atomicAdd(&g_fill[d], 1);
        float w = g_dinv[d] * g_dinv[s];
        g_edge[pos] = make_int2(s, __float_as_int(w));
    }
}

// -------------------- x -> fp16 --------------------
__global__ void xconv_kernel(const float* __restrict__ x) {
    int i = blockIdx.x * blockDim.x + threadIdx.x;  // over NN*F_IN/2
    if (i < NN * F_IN / 2) {
        float2 v = ((const float2*)x)[i];
        ((__half2*)g_hf)[i] = __floats2half2_rn(v.x, v.y);
    }
}

// -------------------- all weight splits in one kernel ------------------------
#define W1SZ (F_IN * H1)
#define W2SZ (H1 * H2)
#define W3SZ (H2 * H3)
__global__ void splitw_all(const float* __restrict__ W1,
                           const float* __restrict__ W2,
                           const float* __restrict__ W3) {
    int i = blockIdx.x * blockDim.x + threadIdx.x;
    float v;
    __half* dh;
    __half* dl;
    int j;
    if (i < W1SZ) {
        j = i; v = W1[j]; dh = g_w1H; dl = g_w1L;
    } else if (i < W1SZ + W2SZ) {
        j = i - W1SZ; v = W2[j]; dh = g_w2H; dl = g_w2L;
    } else if (i < W1SZ + W2SZ + W3SZ) {
        j = i - W1SZ - W2SZ; v = W3[j]; dh = g_w3H; dl = g_w3L;
    } else return;
    __half h = __float2half_rn(v);
    dh[j] = h;
    dl[j] = __float2half_rn(v - __half2float(h));
}

// -------------------- agg1: fp16 x (H=128) -> fp16 output --------------------
__global__ void agg1_kernel() {
    int gw = (blockIdx.x * blockDim.x + threadIdx.x) >> 5;
    int lane = threadIdx.x & 31;
    if (gw >= NN) return;
    const int n = gw;
    const float dd = g_dinv[n];
    const float w0 = dd * dd;

    float acc[4];
    {
        uint2 hv = ((const uint2*)(g_hf + (size_t)n * F_IN))[lane];
        float2 f0 = h2f2(hv.x), f1 = h2f2(hv.y);
        acc[0] = w0 * f0.x; acc[1] = w0 * f0.y;
        acc[2] = w0 * f1.x; acc[3] = w0 * f1.y;
    }

    const int e0 = g_offsets[n], e1 = g_offsets[n + 1];
    for (int e = e0; e < e1; e++) {
        int2 ew = g_edge[e];
        float w = __int_as_float(ew.y);
        uint2 hv = ((const uint2*)(g_hf + (size_t)ew.x * F_IN))[lane];
        float2 f0 = h2f2(hv.x), f1 = h2f2(hv.y);
        acc[0] += w * f0.x; acc[1] += w * f0.y;
        acc[2] += w * f1.x; acc[3] += w * f1.y;
    }

    __half2 o0 = __floats2half2_rn(acc[0], acc[1]);
    __half2 o1 = __floats2half2_rn(acc[2], acc[3]);
    ((uint2*)(g_af + (size_t)n * F_IN))[lane] =
        make_uint2(*(uint32_t*)&o0, *(uint32_t*)&o1);
}

// -------------------- agg23: fp16 input (H=256) -> fp16 output ---------------
__global__ void agg23_kernel() {
    int gw = (blockIdx.x * blockDim.x + threadIdx.x) >> 5;
    int lane = threadIdx.x & 31;
    if (gw >= NN) return;
    const int n = gw;
    const float dd = g_dinv[n];
    const float w0 = dd * dd;

    float acc[8];
    {
        uint4 hv = ((const uint4*)(g_hf + (size_t)n * 256))[lane];
        float2 f0 = h2f2(hv.x), f1 = h2f2(hv.y), f2 = h2f2(hv.z), f3 = h2f2(hv.w);
        acc[0] = w0 * f0.x; acc[1] = w0 * f0.y; acc[2] = w0 * f1.x; acc[3] = w0 * f1.y;
        acc[4] = w0 * f2.x; acc[5] = w0 * f2.y; acc[6] = w0 * f3.x; acc[7] = w0 * f3.y;
    }

    const int e0 = g_offsets[n], e1 = g_offsets[n + 1];
    for (int e = e0; e < e1; e++) {
        int2 ew = g_edge[e];
        float w = __int_as_float(ew.y);
        uint4 hv = ((const uint4*)(g_hf + (size_t)ew.x * 256))[lane];
        float2 f0 = h2f2(hv.x), f1 = h2f2(hv.y), f2 = h2f2(hv.z), f3 = h2f2(hv.w);
        acc[0] += w * f0.x; acc[1] += w * f0.y; acc[2] += w * f1.x; acc[3] += w * f1.y;
        acc[4] += w * f2.x; acc[5] += w * f2.y; acc[6] += w * f3.x; acc[7] += w * f3.y;
    }

    __half2 o0 = __floats2half2_rn(acc[0], acc[1]);
    __half2 o1 = __floats2half2_rn(acc[2], acc[3]);
    __half2 o2 = __floats2half2_rn(acc[4], acc[5]);
    __half2 o3 = __floats2half2_rn(acc[6], acc[7]);
    uint4 ov;
    ov.x = *(uint32_t*)&o0; ov.y = *(uint32_t*)&o1;
    ov.z = *(uint32_t*)&o2; ov.w = *(uint32_t*)&o3;
    ((uint4*)(g_af + (size_t)n * 256))[lane] = ov;
}

// -------------------- GEMM via mma.sync fp16, cp.async double-buffered -------
// CTA tile 128x128, 8 warps (4x2), warp tile 32x64, k-chunk 64, 2-stage pipe.
// A = single fp16 (g_af), W = fp16 hi + residual (WSEL) -> 2 MMA terms.
// Epilogue: tanh(acc + bias) -> fp16 into g_hf (all layers; FC reads fp16 h3).
#define A_PITCH 144   // 64 fp16 = 128B + 16B pad
#define B_PITCH 272   // 128 fp16 = 256B + 16B pad
#define SM_A  0
#define SM_BH (128 * A_PITCH)
#define SM_BL (128 * A_PITCH + 64 * B_PITCH)
#define SM_STG (128 * A_PITCH + 2 * 64 * B_PITCH)
#define SM_TOT (2 * SM_STG)

template <int K, int NB, int WSEL>
__device__ __forceinline__ void gemm_load_chunk(uint32_t sb, int stg, int m0, int n0,
                                                int k0, int t) {
    uint32_t base = sb + stg * SM_STG;
    const __half* wH = wselH(WSEL);
    const __half* wL = wselL(WSEL);
    #pragma unroll
    for (int i = 0; i < 4; i++) {
        int idx = t + i * 256;
        int row = idx >> 3, seg = idx & 7;
        size_t gofs = ((size_t)(m0 + row) * K + k0) * 2 + seg * 16;
        cpa16(base + SM_A + row * A_PITCH + seg * 16, (const char*)g_af + gofs);
    }
    #pragma unroll
    for (int i = 0; i < 4; i++) {
        int idx = t + i * 256;
        int row = idx >> 4, seg = idx & 15;
        size_t gofs = ((size_t)(k0 + row) * NB + n0) * 2 + seg * 16;
        cpa16(base + SM_BH + row * B_PITCH + seg * 16, (const char*)wH + gofs);
        cpa16(base + SM_BL + row * B_PITCH + seg * 16, (const char*)wL + gofs);
    }
    CPA_COMMIT();
}

template <int K, int NB, int WSEL>
__global__ void __launch_bounds__(256, 1)
gemm_mma(const float* __restrict__ bias) {
    extern __shared__ char sm[];
    const uint32_t sb = smem_u32(sm);
    const int t = threadIdx.x;
    const int warp = t >> 5, lane = t & 31;
    const int wm = warp >> 1, wn = warp & 1;
    const int m0 = blockIdx.y * 128, n0 = blockIdx.x * 128;
    constexpr int NCH = K / 64;

    float c[2][8][4];
    #pragma unroll
    for (int i = 0; i < 2; i++)
        #pragma unroll
        for (int j = 0; j < 8; j++)
            #pragma unroll
            for (int q = 0; q < 4; q++) c[i][j][q] = 0.0f;

    gemm_load_chunk<K, NB, WSEL>(sb, 0, m0, n0, 0, t);

    for (int ch = 0; ch < NCH; ch++) {
        CPA_WAIT0();
        __syncthreads();
        if (ch + 1 < NCH)
            gemm_load_chunk<K, NB, WSEL>(sb, (ch + 1) & 1, m0, n0, (ch + 1) * 64, t);

        const char* base = sm + (ch & 1) * SM_STG;
        #pragma unroll
        for (int k16 = 0; k16 < 4; k16++) {
            uint32_t aa[2][4];
            #pragma unroll
            for (int mt = 0; mt < 2; mt++) {
                int row = wm * 32 + mt * 16 + (lane & 15);
                int cb = k16 * 32 + ((lane >> 4) << 4);
                LDSM_X4(aa[mt], smem_u32(base + SM_A + row * A_PITCH + cb));
            }
            uint32_t bh[4][4], bl[4][4];
            #pragma unroll
            for (int np = 0; np < 4; np++) {
                int krow = k16 * 16 + (lane & 7) + (lane & 8);
                int cb = wn * 128 + np * 32 + ((lane >> 4) << 4);
                LDSM_X4T(bh[np], smem_u32(base + SM_BH + krow * B_PITCH + cb));
                LDSM_X4T(bl[np], smem_u32(base + SM_BL + krow * B_PITCH + cb));
            }
            #pragma unroll
            for (int mt = 0; mt < 2; mt++) {
                #pragma unroll
                for (int np = 0; np < 4; np++) {
                    mma16816h(c[mt][np * 2],     aa[mt], bh[np][0], bh[np][1]);
                    mma16816h(c[mt][np * 2],     aa[mt], bl[np][0], bl[np][1]);
                    mma16816h(c[mt][np * 2 + 1], aa[mt], bh[np][2], bh[np][3]);
                    mma16816h(c[mt][np * 2 + 1], aa[mt], bl[np][2], bl[np][3]);
                }
            }
        }
        __syncthreads();
    }

    // epilogue: tanh(acc + bias) -> fp16 into g_hf
    const int g = lane >> 2, tq = lane & 3;
    #pragma unroll
    for (int mt = 0; mt < 2; mt++) {
        int row = m0 + wm * 32 + mt * 16 + g;
        #pragma unroll
        for (int n8 = 0; n8 < 8; n8++) {
            int col = n0 + wn * 64 + n8 * 8 + 2 * tq;
            float b0 = __ldg(bias + col), b1 = __ldg(bias + col + 1);
            float v0 = tanhf(c[mt][n8][0] + b0);
            float v1 = tanhf(c[mt][n8][1] + b1);
            float v2 = tanhf(c[mt][n8][2] + b0);
            float v3 = tanhf(c[mt][n8][3] + b1);
            *(__half2*)(g_hf + (size_t)row * NB + col) = __floats2half2_rn(v0, v1);
            *(__half2*)(g_hf + (size_t)(row + 8) * NB + col) = __floats2half2_rn(v2, v3);
        }
    }
}

// -------------------- final FC: out[64,64] = h3.reshape(64,128000) @ Wfc + bfc
__global__ void fc_init(const float* __restrict__ bfc, float* __restrict__ out) {
    int i = blockIdx.x * blockDim.x + threadIdx.x;
    if (i < NG * OUTD) out[i] = bfc[i & 63];
}

#define FC_KCH 512
__global__ void fc_kernel(const float* __restrict__ Wfc,
                          float* __restrict__ out) {
    const __half* __restrict__ h3 = g_hf;   // fp16 h3 after layer-3 GEMM
    __shared__ float Ws[16][64];
    __shared__ float Hs[64][17];
    const int t = threadIdx.x;
    const int tg = t & 15;
    const int to = t >> 4;
    float acc[4][4];
    #pragma unroll
    for (int i = 0; i < 4; i++)
        #pragma unroll
        for (int j = 0; j < 4; j++) acc[i][j] = 0.0f;

    const int kbase = blockIdx.x * FC_KCH;
    for (int kk0 = 0; kk0 < FC_KCH; kk0 += 16) {
        const int k0 = kbase + kk0;
        #pragma unroll
        for (int rr = 0; rr < 4; rr++) {
            int idx = t + rr * 256;
            int kr = idx >> 6, nn = idx & 63;
            Ws[kr][nn] = Wfc[(size_t)(k0 + kr) * OUTD + nn];
        }
        #pragma unroll
        for (int rr = 0; rr < 4; rr++) {
            int idx = t + rr * 256;
            int g = idx >> 4, kk = idx & 15;
            Hs[g][kk] = __half2float(h3[(size_t)g * 128000 + k0 + kk]);
        }
        __syncthreads();
        #pragma unroll
        for (int kk = 0; kk < 16; kk++) {
            float hv[4], wv[4];
            #pragma unroll
            for (int i = 0; i < 4; i++) hv[i] = Hs[4 * tg + i][kk];
            #pragma unroll
            for (int j = 0; j < 4; j++) wv[j] = Ws[kk][4 * to + j];
            #pragma unroll
            for (int i = 0; i < 4; i++)
                #pragma unroll
                for (int j = 0; j < 4; j++) acc[i][j] += hv[i] * wv[j];
        }
        __syncthreads();
    }
    #pragma unroll
    for (int i = 0; i < 4; i++)
        #pragma unroll
        for (int j = 0; j < 4; j++)
            atomicAdd(&out[(4 * tg + i) * OUTD + 4 * to + j], acc[i][j]);
}

// -------------------- launch --------------------
extern "C" void kernel_launch(void* const* d_in, const int* in_sizes, int n_in,
                              void* d_out, int out_size) {
    const float* x   = (const float*)d_in[0];
    const void*  ei  = d_in[1];
    const float* W1  = (const float*)d_in[3];
    const float* b1  = (const float*)d_in[4];
    const float* W2  = (const float*)d_in[5];
    const float* b2  = (const float*)d_in[6];
    const float* W3  = (const float*)d_in[7];
    const float* b3  = (const float*)d_in[8];
    const float* Wfc = (const float*)d_in[9];
    const float* bfc = (const float*)d_in[10];
    float* out = (float*)d_out;

    cudaFuncSetAttribute(gemm_mma<F_IN, H1, 1>, cudaFuncAttributeMaxDynamicSharedMemorySize, SM_TOT);
    cudaFuncSetAttribute(gemm_mma<H1, H2, 2>,   cudaFuncAttributeMaxDynamicSharedMemorySize, SM_TOT);
    cudaFuncSetAttribute(gemm_mma<H2, H3, 3>,   cudaFuncAttributeMaxDynamicSharedMemorySize, SM_TOT);

    // preprocessing (weights split up front; edge pipeline)
    splitw_all<<<(W1SZ + W2SZ + W3SZ + 255) / 256, 256>>>(W1, W2, W3);
    detect_kernel<<<1, 1>>>(ei);
    zero_kernel<<<(NN + 255) / 256, 256>>>();
    hist_kernel<<<EE / 256, 256>>>(ei);
    reduce_kernel<<<NN / 256, 256>>>();
    scanpart_kernel<<<1, 256>>>();
    blockscan_kernel<<<NN / 256, 256>>>();
    scatter_kernel<<<EE / 256, 256>>>(ei);
    xconv_kernel<<<(NN * F_IN / 2 + 255) / 256, 256>>>(x);

    const int aggBlocks = (NN * 32) / 256;

    // layer 1: agg-first (Â x, fp16 gather) then GEMM(128->256), tanh -> fp16
    agg1_kernel<<<aggBlocks, 256>>>();
    gemm_mma<F_IN, H1, 1><<<dim3(H1 / 128, NN / 128), 256, SM_TOT>>>(b1);

    // layer 2: agg (fp16 gather, 256) then GEMM(256->256), tanh -> fp16
    agg23_kernel<<<aggBlocks, 256>>>();
    gemm_mma<H1, H2, 2><<<dim3(H2 / 128, NN / 128), 256, SM_TOT>>>(b2);

    // layer 3: agg then GEMM(256->128), tanh -> fp16 h3
    agg23_kernel<<<aggBlocks, 256>>>();
    gemm_mma<H2, H3, 3><<<dim3(H3 / 128, NN / 128), 256, SM_TOT>>>(b3);

    // final FC (fp16 h3) with split-K atomics
    fc_init<<<(NG * OUTD + 255) / 256, 256>>>(bfc, out);
    fc_kernel<<<128000 / FC_KCH, 256>>>(Wfc, out);
}

// round 13
// speedup vs baseline: 1.6075x; 1.0564x over previous
#include <cuda_runtime.h>
#include <cuda_bf16.h>
#include <cuda_fp16.h>
#include <cstdint>
#include <cstddef>

// Problem constants (fixed by the dataset)
#define NN 64000
#define EE 1048576
#define NG 64
#define NBN 1000
#define F_IN 128
#define H1 256
#define H2 256
#define H3 128
#define OUTD 64

// -------------------- scratch (device globals; no allocs) --------------------
__device__ __align__(16) __half g_af[(size_t)NN * 256];    // fp16 aggregated (GEMM A)
__device__ __align__(16) __half g_hf[(size_t)NN * 256];    // fp16 activations (gather src / h3)
__device__ __align__(16) __half g_w1H[F_IN * H1], g_w1L[F_IN * H1];
__device__ __align__(16) __half g_w2H[H1 * H2],  g_w2L[H1 * H2];
__device__ __align__(16) __half g_w3H[H2 * H3],  g_w3L[H2 * H3];
__device__ int2  g_edge[EE];                               // {src, w = dinv[d]*dinv[s]}
__device__ __align__(16) int g_counts[NN];
__device__ int   g_offsets[NN + 1];
__device__ __align__(16) int g_fill[NN];
__device__ float g_dinv[NN];
__device__ int   g_isI64;
__device__ int   g_bsum[256];
__device__ int   g_boff[256];

__device__ __forceinline__ int ei_at(const void* ei, size_t idx) {
    if (g_isI64) return (int)((const long long*)ei)[idx];
    return ((const int*)ei)[idx];
}

// weight-buffer selector (device-side only)
__device__ __forceinline__ const __half* wselH(int s) {
    return s == 1 ? g_w1H : (s == 2 ? g_w2H : g_w3H);
}
__device__ __forceinline__ const __half* wselL(int s) {
    return s == 1 ? g_w1L : (s == 2 ? g_w2L : g_w3L);
}

// -------------------- PTX helpers (family-generic sm_80+ features only) ------
__device__ __forceinline__ uint32_t smem_u32(const void* p) {
    uint32_t a;
    asm("{ .reg .u64 t; cvta.to.shared.u64 t, %1; cvt.u32.u64 %0, t; }" : "=r"(a) : "l"(p));
    return a;
}
__device__ __forceinline__ void cpa16(uint32_t s, const void* g) {
    asm volatile("cp.async.cg.shared.global [%0], [%1], 16;" :: "r"(s), "l"(g) : "memory");
}
#define CPA_COMMIT() asm volatile("cp.async.commit_group;" ::: "memory")
#define CPA_WAIT0()  asm volatile("cp.async.wait_group 0;" ::: "memory")
#define CPA_WAIT1()  asm volatile("cp.async.wait_group 1;" ::: "memory")

#define LDSM_X4(r, a)                                                              \
    asm volatile("ldmatrix.sync.aligned.m8n8.x4.shared.b16 {%0,%1,%2,%3}, [%4];"   \
                 : "=r"((r)[0]), "=r"((r)[1]), "=r"((r)[2]), "=r"((r)[3]) : "r"(a))
#define LDSM_X4T(r, a)                                                                  \
    asm volatile("ldmatrix.sync.aligned.m8n8.x4.trans.shared.b16 {%0,%1,%2,%3}, [%4];"  \
                 : "=r"((r)[0]), "=r"((r)[1]), "=r"((r)[2]), "=r"((r)[3]) : "r"(a))

__device__ __forceinline__ void mma16816h(float* c, const uint32_t* a,
                                          uint32_t b0, uint32_t b1) {
    asm volatile(
        "mma.sync.aligned.m16n8k16.row.col.f32.f16.f16.f32 "
        "{%0,%1,%2,%3}, {%4,%5,%6,%7}, {%8,%9}, {%0,%1,%2,%3};"
        : "+f"(c[0]), "+f"(c[1]), "+f"(c[2]), "+f"(c[3])
        : "r"(a[0]), "r"(a[1]), "r"(a[2]), "r"(a[3]), "r"(b0), "r"(b1));
}

__device__ __forceinline__ float2 h2f2(uint32_t u) {
    return __half22float2(*(__half2*)&u);
}

// -------------------- dtype detection --------------------
__global__ void detect_kernel(const void* ei) {
    const unsigned int* w = (const unsigned int*)ei;
    int is64 = 1;
    #pragma unroll
    for (int i = 0; i < 32; i++)
        if (w[2 * i + 1] != 0u) is64 = 0;
    g_isI64 = is64;
}

// -------------------- preprocessing --------------------
__global__ void zero_kernel() {
    int i = blockIdx.x * blockDim.x + threadIdx.x;   // over NN/4
    if (i < NN / 4) {
        ((int4*)g_counts)[i] = make_int4(0, 0, 0, 0);
        ((int4*)g_fill)[i] = make_int4(0, 0, 0, 0);
    }
}

__global__ void hist_kernel(const void* __restrict__ ei) {
    int e = blockIdx.x * blockDim.x + threadIdx.x;
    if (e < EE) {
        int d = ei_at(ei, (size_t)EE + e);
        atomicAdd(&g_counts[d], 1);
    }
}

__global__ void reduce_kernel() {
    int b = blockIdx.x;
    int v = g_counts[b * 256 + threadIdx.x];
    #pragma unroll
    for (int o = 16; o; o >>= 1) v += __shfl_down_sync(0xffffffffu, v, o);
    __shared__ int ws[8];
    if ((threadIdx.x & 31) == 0) ws[threadIdx.x >> 5] = v;
    __syncthreads();
    if (threadIdx.x == 0) {
        int s = 0;
        #pragma unroll
        for (int i = 0; i < 8; i++) s += ws[i];
        g_bsum[b] = s;
    }
}

__global__ void scanpart_kernel() {
    int t = threadIdx.x;
    int v = (t < NN / 256) ? g_bsum[t] : 0;
    int lane = t & 31, w = t >> 5;
    int x = v;
    #pragma unroll
    for (int o = 1; o < 32; o <<= 1) {
        int y = __shfl_up_sync(0xffffffffu, x, o);
        if (lane >= o) x += y;
    }
    __shared__ int ws[8], wso[8];
    if (lane == 31) ws[w] = x;
    __syncthreads();
    if (t < 8) {
        int s = 0;
        for (int i = 0; i < t; i++) s += ws[i];
        wso[t] = s;
    }
    __syncthreads();
    int incl = x + wso[w];
    if (t < NN / 256) g_boff[t] = incl - v;
    if (t == 255) g_offsets[NN] = incl;
}

__global__ void blockscan_kernel() {
    int b = blockIdx.x, t = threadIdx.x, i = b * 256 + t;
    int c = g_counts[i];
    int lane = t & 31, w = t >> 5;
    int x = c;
    #pragma unroll
    for (int o = 1; o < 32; o <<= 1) {
        int y = __shfl_up_sync(0xffffffffu, x, o);
        if (lane >= o) x += y;
    }
    __shared__ int ws[8], wso[8];
    if (lane == 31) ws[w] = x;
    __syncthreads();
    if (t < 8) {
        int s = 0;
        for (int j = 0; j < t; j++) s += ws[j];
        wso[t] = s;
    }
    __syncthreads();
    g_offsets[i] = x - c + wso[w] + g_boff[b];
    g_dinv[i] = rsqrtf((float)(c + 1));
}

// scatter dst-sorted edge records {src, dinv[d]*dinv[s]} (needs g_dinv ready)
__global__ void scatter_kernel(const void* __restrict__ ei) {
    int e = blockIdx.x * blockDim.x + threadIdx.x;
    if (e < EE) {
        int d = ei_at(ei, (size_t)EE + e);
        int s = ei_at(ei, (size_t)e);
        int pos = g_offsets[d] + atomicAdd(&g_fill[d], 1);
        float w = g_dinv[d] * g_dinv[s];
        g_edge[pos] = make_int2(s, __float_as_int(w));
    }
}

// -------------------- x -> fp16 --------------------
__global__ void xconv_kernel(const float* __restrict__ x) {
    int i = blockIdx.x * blockDim.x + threadIdx.x;  // over NN*F_IN/2
    if (i < NN * F_IN / 2) {
        float2 v = ((const float2*)x)[i];
        ((__half2*)g_hf)[i] = __floats2half2_rn(v.x, v.y);
    }
}

// -------------------- all weight splits in one kernel ------------------------
#define W1SZ (F_IN * H1)
#define W2SZ (H1 * H2)
#define W3SZ (H2 * H3)
__global__ void splitw_all(const float* __restrict__ W1,
                           const float* __restrict__ W2,
                           const float* __restrict__ W3) {
    int i = blockIdx.x * blockDim.x + threadIdx.x;
    float v;
    __half* dh;
    __half* dl;
    int j;
    if (i < W1SZ) {
        j = i; v = W1[j]; dh = g_w1H; dl = g_w1L;
    } else if (i < W1SZ + W2SZ) {
        j = i - W1SZ; v = W2[j]; dh = g_w2H; dl = g_w2L;
    } else if (i < W1SZ + W2SZ + W3SZ) {
        j = i - W1SZ - W2SZ; v = W3[j]; dh = g_w3H; dl = g_w3L;
    } else return;
    __half h = __float2half_rn(v);
    dh[j] = h;
    dl[j] = __float2half_rn(v - __half2float(h));
}

// -------------------- agg1: fp16 x (H=128) -> fp16 output --------------------
__global__ void agg1_kernel() {
    int gw = (blockIdx.x * blockDim.x + threadIdx.x) >> 5;
    int lane = threadIdx.x & 31;
    if (gw >= NN) return;
    const int n = gw;
    const float dd = g_dinv[n];
    const float w0 = dd * dd;

    float acc[4];
    {
        uint2 hv = ((const uint2*)(g_hf + (size_t)n * F_IN))[lane];
        float2 f0 = h2f2(hv.x), f1 = h2f2(hv.y);
        acc[0] = w0 * f0.x; acc[1] = w0 * f0.y;
        acc[2] = w0 * f1.x; acc[3] = w0 * f1.y;
    }

    const int e0 = g_offsets[n], e1 = g_offsets[n + 1];
    for (int e = e0; e < e1; e++) {
        int2 ew = g_edge[e];
        float w = __int_as_float(ew.y);
        uint2 hv = ((const uint2*)(g_hf + (size_t)ew.x * F_IN))[lane];
        float2 f0 = h2f2(hv.x), f1 = h2f2(hv.y);
        acc[0] += w * f0.x; acc[1] += w * f0.y;
        acc[2] += w * f1.x; acc[3] += w * f1.y;
    }

    __half2 o0 = __floats2half2_rn(acc[0], acc[1]);
    __half2 o1 = __floats2half2_rn(acc[2], acc[3]);
    ((uint2*)(g_af + (size_t)n * F_IN))[lane] =
        make_uint2(*(uint32_t*)&o0, *(uint32_t*)&o1);
}

// -------------------- agg23: fp16 input (H=256) -> fp16 output ---------------
__global__ void agg23_kernel() {
    int gw = (blockIdx.x * blockDim.x + threadIdx.x) >> 5;
    int lane = threadIdx.x & 31;
    if (gw >= NN) return;
    const int n = gw;
    const float dd = g_dinv[n];
    const float w0 = dd * dd;

    float acc[8];
    {
        uint4 hv = ((const uint4*)(g_hf + (size_t)n * 256))[lane];
        float2 f0 = h2f2(hv.x), f1 = h2f2(hv.y), f2 = h2f2(hv.z), f3 = h2f2(hv.w);
        acc[0] = w0 * f0.x; acc[1] = w0 * f0.y; acc[2] = w0 * f1.x; acc[3] = w0 * f1.y;
        acc[4] = w0 * f2.x; acc[5] = w0 * f2.y; acc[6] = w0 * f3.x; acc[7] = w0 * f3.y;
    }

    const int e0 = g_offsets[n], e1 = g_offsets[n + 1];
    for (int e = e0; e < e1; e++) {
        int2 ew = g_edge[e];
        float w = __int_as_float(ew.y);
        uint4 hv = ((const uint4*)(g_hf + (size_t)ew.x * 256))[lane];
        float2 f0 = h2f2(hv.x), f1 = h2f2(hv.y), f2 = h2f2(hv.z), f3 = h2f2(hv.w);
        acc[0] += w * f0.x; acc[1] += w * f0.y; acc[2] += w * f1.x; acc[3] += w * f1.y;
        acc[4] += w * f2.x; acc[5] += w * f2.y; acc[6] += w * f3.x; acc[7] += w * f3.y;
    }

    __half2 o0 = __floats2half2_rn(acc[0], acc[1]);
    __half2 o1 = __floats2half2_rn(acc[2], acc[3]);
    __half2 o2 = __floats2half2_rn(acc[4], acc[5]);
    __half2 o3 = __floats2half2_rn(acc[6], acc[7]);
    uint4 ov;
    ov.x = *(uint32_t*)&o0; ov.y = *(uint32_t*)&o1;
    ov.z = *(uint32_t*)&o2; ov.w = *(uint32_t*)&o3;
    ((uint4*)(g_af + (size_t)n * 256))[lane] = ov;
}

// -------------------- GEMM via mma.sync fp16, 3-stage cp.async, occ 2 --------
// CTA tile 128x128, 8 warps (4x2), warp tile 32x64, k-chunk 32, 3-stage ring.
// A = single fp16 (g_af), W = fp16 hi + residual (WSEL) -> 2 MMA terms.
// Epilogue: tanh(acc + bias) -> fp16 into g_hf (all layers; FC reads fp16 h3).
#define A_PITCH 80    // 32 fp16 = 64B + 16B pad
#define B_PITCH 272   // 128 fp16 = 256B + 16B pad
#define SM_A  0
#define SM_BH (128 * A_PITCH)
#define SM_BL (128 * A_PITCH + 32 * B_PITCH)
#define SM_STG (128 * A_PITCH + 2 * 32 * B_PITCH)   // 27648 B
#define SM_TOT (3 * SM_STG)                         // 82944 B

template <int K, int NB, int WSEL>
__device__ __forceinline__ void gemm_load_chunk(uint32_t sb, int stg, int m0, int n0,
                                                int k0, int t) {
    uint32_t base = sb + stg * SM_STG;
    const __half* wH = wselH(WSEL);
    const __half* wL = wselL(WSEL);
    // A: 128 rows x 32 fp16 (64B = 4 x 16B segs) -> 512 cpa16 (2/thread)
    #pragma unroll
    for (int i = 0; i < 2; i++) {
        int idx = t + i * 256;
        int row = idx >> 2, seg = idx & 3;
        size_t gofs = ((size_t)(m0 + row) * K + k0) * 2 + seg * 16;
        cpa16(base + SM_A + row * A_PITCH + seg * 16, (const char*)g_af + gofs);
    }
    // B: 2 arrays x 32 rows x 128 fp16 (256B = 16 segs) -> 1024 cpa16 (4/thread)
    #pragma unroll
    for (int i = 0; i < 2; i++) {
        int idx = t + i * 256;
        int row = idx >> 4, seg = idx & 15;
        size_t gofs = ((size_t)(k0 + row) * NB + n0) * 2 + seg * 16;
        cpa16(base + SM_BH + row * B_PITCH + seg * 16, (const char*)wH + gofs);
        cpa16(base + SM_BL + row * B_PITCH + seg * 16, (const char*)wL + gofs);
    }
    CPA_COMMIT();
}

template <int K, int NB, int WSEL>
__global__ void __launch_bounds__(256, 2)
gemm_mma(const float* __restrict__ bias) {
    extern __shared__ char sm[];
    const uint32_t sb = smem_u32(sm);
    const int t = threadIdx.x;
    const int warp = t >> 5, lane = t & 31;
    const int wm = warp >> 1, wn = warp & 1;
    const int m0 = blockIdx.y * 128, n0 = blockIdx.x * 128;
    constexpr int NCH = K / 32;

    float c[2][8][4];
    #pragma unroll
    for (int i = 0; i < 2; i++)
        #pragma unroll
        for (int j = 0; j < 8; j++)
            #pragma unroll
            for (int q = 0; q < 4; q++) c[i][j][q] = 0.0f;

    gemm_load_chunk<K, NB, WSEL>(sb, 0, m0, n0, 0, t);
    gemm_load_chunk<K, NB, WSEL>(sb, 1, m0, n0, 32, t);

    for (int ch = 0; ch < NCH; ch++) {
        if (ch + 1 < NCH) { CPA_WAIT1(); } else { CPA_WAIT0(); }
        __syncthreads();
        if (ch + 2 < NCH)
            gemm_load_chunk<K, NB, WSEL>(sb, (ch + 2) % 3, m0, n0, (ch + 2) * 32, t);

        const char* base = sm + (ch % 3) * SM_STG;
        #pragma unroll
        for (int k16 = 0; k16 < 2; k16++) {
            uint32_t aa[2][4];
            #pragma unroll
            for (int mt = 0; mt < 2; mt++) {
                int row = wm * 32 + mt * 16 + (lane & 15);
                int cb = k16 * 32 + ((lane >> 4) << 4);
                LDSM_X4(aa[mt], smem_u32(base + SM_A + row * A_PITCH + cb));
            }
            uint32_t bh[4][4], bl[4][4];
            #pragma unroll
            for (int np = 0; np < 4; np++) {
                int krow = k16 * 16 + (lane & 7) + (lane & 8);
                int cb = wn * 128 + np * 32 + ((lane >> 4) << 4);
                LDSM_X4T(bh[np], smem_u32(base + SM_BH + krow * B_PITCH + cb));
                LDSM_X4T(bl[np], smem_u32(base + SM_BL + krow * B_PITCH + cb));
            }
            #pragma unroll
            for (int mt = 0; mt < 2; mt++) {
                #pragma unroll
                for (int np = 0; np < 4; np++) {
                    mma16816h(c[mt][np * 2],     aa[mt], bh[np][0], bh[np][1]);
                    mma16816h(c[mt][np * 2],     aa[mt], bl[np][0], bl[np][1]);
                    mma16816h(c[mt][np * 2 + 1], aa[mt], bh[np][2], bh[np][3]);
                    mma16816h(c[mt][np * 2 + 1], aa[mt], bl[np][2], bl[np][3]);
                }
            }
        }
        __syncthreads();
    }

    // epilogue: tanh(acc + bias) -> fp16 into g_hf
    const int g = lane >> 2, tq = lane & 3;
    #pragma unroll
    for (int mt = 0; mt < 2; mt++) {
        int row = m0 + wm * 32 + mt * 16 + g;
        #pragma unroll
        for (int n8 = 0; n8 < 8; n8++) {
            int col = n0 + wn * 64 + n8 * 8 + 2 * tq;
            float b0 = __ldg(bias + col), b1 = __ldg(bias + col + 1);
            float v0 = tanhf(c[mt][n8][0] + b0);
            float v1 = tanhf(c[mt][n8][1] + b1);
            float v2 = tanhf(c[mt][n8][2] + b0);
            float v3 = tanhf(c[mt][n8][3] + b1);
            *(__half2*)(g_hf + (size_t)row * NB + col) = __floats2half2_rn(v0, v1);
            *(__half2*)(g_hf + (size_t)(row + 8) * NB + col) = __floats2half2_rn(v2, v3);
        }
    }
}

// -------------------- final FC: out[64,64] = h3.reshape(64,128000) @ Wfc + bfc
__global__ void fc_init(const float* __restrict__ bfc, float* __restrict__ out) {
    int i = blockIdx.x * blockDim.x + threadIdx.x;
    if (i < NG * OUTD) out[i] = bfc[i & 63];
}

#define FC_KCH 512
__global__ void fc_kernel(const float* __restrict__ Wfc,
                          float* __restrict__ out) {
    const __half* __restrict__ h3 = g_hf;   // fp16 h3 after layer-3 GEMM
    __shared__ float Ws[16][64];
    __shared__ float Hs[64][17];
    const int t = threadIdx.x;
    const int tg = t & 15;
    const int to = t >> 4;
    float acc[4][4];
    #pragma unroll
    for (int i = 0; i < 4; i++)
        #pragma unroll
        for (int j = 0; j < 4; j++) acc[i][j] = 0.0f;

    const int kbase = blockIdx.x * FC_KCH;
    for (int kk0 = 0; kk0 < FC_KCH; kk0 += 16) {
        const int k0 = kbase + kk0;
        #pragma unroll
        for (int rr = 0; rr < 4; rr++) {
            int idx = t + rr * 256;
            int kr = idx >> 6, nn = idx & 63;
            Ws[kr][nn] = Wfc[(size_t)(k0 + kr) * OUTD + nn];
        }
        #pragma unroll
        for (int rr = 0; rr < 4; rr++) {
            int idx = t + rr * 256;
            int g = idx >> 4, kk = idx & 15;
            Hs[g][kk] = __half2float(h3[(size_t)g * 128000 + k0 + kk]);
        }
        __syncthreads();
        #pragma unroll
        for (int kk = 0; kk < 16; kk++) {
            float hv[4], wv[4];
            #pragma unroll
            for (int i = 0; i < 4; i++) hv[i] = Hs[4 * tg + i][kk];
            #pragma unroll
            for (int j = 0; j < 4; j++) wv[j] = Ws[kk][4 * to + j];
            #pragma unroll
            for (int i = 0; i < 4; i++)
                #pragma unroll
                for (int j = 0; j < 4; j++) acc[i][j] += hv[i] * wv[j];
        }
        __syncthreads();
    }
    #pragma unroll
    for (int i = 0; i < 4; i++)
        #pragma unroll
        for (int j = 0; j < 4; j++)
            atomicAdd(&out[(4 * tg + i) * OUTD + 4 * to + j], acc[i][j]);
}

// -------------------- launch --------------------
extern "C" void kernel_launch(void* const* d_in, const int* in_sizes, int n_in,
                              void* d_out, int out_size) {
    const float* x   = (const float*)d_in[0];
    const void*  ei  = d_in[1];
    const float* W1  = (const float*)d_in[3];
    const float* b1  = (const float*)d_in[4];
    const float* W2  = (const float*)d_in[5];
    const float* b2  = (const float*)d_in[6];
    const float* W3  = (const float*)d_in[7];
    const float* b3  = (const float*)d_in[8];
    const float* Wfc = (const float*)d_in[9];
    const float* bfc = (const float*)d_in[10];
    float* out = (float*)d_out;

    cudaFuncSetAttribute(gemm_mma<F_IN, H1, 1>, cudaFuncAttributeMaxDynamicSharedMemorySize, SM_TOT);
    cudaFuncSetAttribute(gemm_mma<H1, H2, 2>,   cudaFuncAttributeMaxDynamicSharedMemorySize, SM_TOT);
    cudaFuncSetAttribute(gemm_mma<H2, H3, 3>,   cudaFuncAttributeMaxDynamicSharedMemorySize, SM_TOT);

    // preprocessing (weights split up front; edge pipeline)
    splitw_all<<<(W1SZ + W2SZ + W3SZ + 255) / 256, 256>>>(W1, W2, W3);
    detect_kernel<<<1, 1>>>(ei);
    zero_kernel<<<(NN / 4 + 255) / 256, 256>>>();
    hist_kernel<<<EE / 256, 256>>>(ei);
    reduce_kernel<<<NN / 256, 256>>>();
    scanpart_kernel<<<1, 256>>>();
    blockscan_kernel<<<NN / 256, 256>>>();
    scatter_kernel<<<EE / 256, 256>>>(ei);
    xconv_kernel<<<(NN * F_IN / 2 + 255) / 256, 256>>>(x);

    const int aggBlocks = (NN * 32) / 256;

    // layer 1: agg-first (Â x, fp16 gather) then GEMM(128->256), tanh -> fp16
    agg1_kernel<<<aggBlocks, 256>>>();
    gemm_mma<F_IN, H1, 1><<<dim3(H1 / 128, NN / 128), 256, SM_TOT>>>(b1);

    // layer 2: agg (fp16 gather, 256) then GEMM(256->256), tanh -> fp16
    agg23_kernel<<<aggBlocks, 256>>>();
    gemm_mma<H1, H2, 2><<<dim3(H2 / 128, NN / 128), 256, SM_TOT>>>(b2);

    // layer 3: agg then GEMM(256->128), tanh -> fp16 h3
    agg23_kernel<<<aggBlocks, 256>>>();
    gemm_mma<H2, H3, 3><<<dim3(H3 / 128, NN / 128), 256, SM_TOT>>>(b3);

    // final FC (fp16 h3) with split-K atomics
    fc_init<<<(NG * OUTD + 255) / 256, 256>>>(bfc, out);
    fc_kernel<<<128000 / FC_KCH, 256>>>(Wfc, out);
}

// round 15
// speedup vs baseline: 1.6316x; 1.0150x over previous
#include <cuda_runtime.h>
#include <cuda_bf16.h>
#include <cuda_fp16.h>
#include <cstdint>
#include <cstddef>

// Problem constants (fixed by the dataset)
#define NN 64000
#define EE 1048576
#define NG 64
#define NBN 1000
#define F_IN 128
#define H1 256
#define H2 256
#define H3 128
#define OUTD 64

// -------------------- scratch (device globals; no allocs) --------------------
__device__ __align__(16) __half g_af[(size_t)NN * 256];    // fp16 aggregated (GEMM A)
__device__ __align__(16) __half g_hf[(size_t)NN * 256];    // fp16 activations (gather src / h3)
__device__ __align__(16) __half g_w1H[F_IN * H1], g_w1L[F_IN * H1];
__device__ __align__(16) __half g_w2H[H1 * H2],  g_w2L[H1 * H2];
__device__ __align__(16) __half g_w3H[H2 * H3],  g_w3L[H2 * H3];
__device__ int2  g_edge[EE];                               // {src, w = dinv[d]*dinv[s]}
__device__ __align__(16) int g_counts[NN];
__device__ int   g_offsets[NN + 1];
__device__ __align__(16) int g_fill[NN];
__device__ float g_dinv[NN];
__device__ int   g_isI64;
__device__ int   g_bsum[256];
__device__ int   g_boff[256];

__device__ __forceinline__ int ei_at(const void* ei, size_t idx) {
    if (g_isI64) return (int)((const long long*)ei)[idx];
    return ((const int*)ei)[idx];
}

// weight-buffer selector (device-side only)
__device__ __forceinline__ const __half* wselH(int s) {
    return s == 1 ? g_w1H : (s == 2 ? g_w2H : g_w3H);
}
__device__ __forceinline__ const __half* wselL(int s) {
    return s == 1 ? g_w1L : (s == 2 ? g_w2L : g_w3L);
}

// -------------------- PTX helpers (family-generic sm_80+ features only) ------
__device__ __forceinline__ uint32_t smem_u32(const void* p) {
    uint32_t a;
    asm("{ .reg .u64 t; cvta.to.shared.u64 t, %1; cvt.u32.u64 %0, t; }" : "=r"(a) : "l"(p));
    return a;
}
__device__ __forceinline__ void cpa16(uint32_t s, const void* g) {
    asm volatile("cp.async.cg.shared.global [%0], [%1], 16;" :: "r"(s), "l"(g) : "memory");
}
#define CPA_COMMIT() asm volatile("cp.async.commit_group;" ::: "memory")
#define CPA_WAIT0()  asm volatile("cp.async.wait_group 0;" ::: "memory")
#define CPA_WAIT1()  asm volatile("cp.async.wait_group 1;" ::: "memory")

#define LDSM_X4(r, a)                                                              \
    asm volatile("ldmatrix.sync.aligned.m8n8.x4.shared.b16 {%0,%1,%2,%3}, [%4];"   \
                 : "=r"((r)[0]), "=r"((r)[1]), "=r"((r)[2]), "=r"((r)[3]) : "r"(a))
#define LDSM_X4T(r, a)                                                                  \
    asm volatile("ldmatrix.sync.aligned.m8n8.x4.trans.shared.b16 {%0,%1,%2,%3}, [%4];"  \
                 : "=r"((r)[0]), "=r"((r)[1]), "=r"((r)[2]), "=r"((r)[3]) : "r"(a))

__device__ __forceinline__ void mma16816h(float* c, const uint32_t* a,
                                          uint32_t b0, uint32_t b1) {
    asm volatile(
        "mma.sync.aligned.m16n8k16.row.col.f32.f16.f16.f32 "
        "{%0,%1,%2,%3}, {%4,%5,%6,%7}, {%8,%9}, {%0,%1,%2,%3};"
        : "+f"(c[0]), "+f"(c[1]), "+f"(c[2]), "+f"(c[3])
        : "r"(a[0]), "r"(a[1]), "r"(a[2]), "r"(a[3]), "r"(b0), "r"(b1));
}

__device__ __forceinline__ float2 h2f2(uint32_t u) {
    return __half22float2(*(__half2*)&u);
}

// packed f32x2 helpers (FFMA2 only reachable via PTX)
__device__ __forceinline__ unsigned long long pack2(float x, float y) {
    unsigned long long r;
    asm("mov.b64 %0, {%1, %2};" : "=l"(r) : "f"(x), "f"(y));
    return r;
}
__device__ __forceinline__ void unpack2(unsigned long long p, float& x, float& y) {
    asm("mov.b64 {%0, %1}, %2;" : "=f"(x), "=f"(y) : "l"(p));
}
#define FFMA2(acc, ap, bp) \
    asm("fma.rn.f32x2 %0, %1, %2, %0;" : "+l"(acc) : "l"(ap), "l"(bp))

// -------------------- preprocessing --------------------
// zero + dtype detection fused (detect by block 0 thread 0; hist runs after)
__global__ void zero_kernel(const void* ei) {
    int i = blockIdx.x * blockDim.x + threadIdx.x;   // over NN/4
    if (i < NN / 4) {
        ((int4*)g_counts)[i] = make_int4(0, 0, 0, 0);
        ((int4*)g_fill)[i] = make_int4(0, 0, 0, 0);
    }
    if (blockIdx.x == 0 && threadIdx.x == 0) {
        const unsigned int* w = (const unsigned int*)ei;
        int is64 = 1;
        #pragma unroll
        for (int k = 0; k < 32; k++)
            if (w[2 * k + 1] != 0u) is64 = 0;
        g_isI64 = is64;
    }
}

__global__ void hist_kernel(const void* __restrict__ ei) {
    int e = blockIdx.x * blockDim.x + threadIdx.x;
    if (e < EE) {
        int d = ei_at(ei, (size_t)EE + e);
        atomicAdd(&g_counts[d], 1);
    }
}

__global__ void reduce_kernel() {
    int b = blockIdx.x;
    int v = g_counts[b * 256 + threadIdx.x];
    #pragma unroll
    for (int o = 16; o; o >>= 1) v += __shfl_down_sync(0xffffffffu, v, o);
    __shared__ int ws[8];
    if ((threadIdx.x & 31) == 0) ws[threadIdx.x >> 5] = v;
    __syncthreads();
    if (threadIdx.x == 0) {
        int s = 0;
        #pragma unroll
        for (int i = 0; i < 8; i++) s += ws[i];
        g_bsum[b] = s;
    }
}

__global__ void scanpart_kernel() {
    int t = threadIdx.x;
    int v = (t < NN / 256) ? g_bsum[t] : 0;
    int lane = t & 31, w = t >> 5;
    int x = v;
    #pragma unroll
    for (int o = 1; o < 32; o <<= 1) {
        int y = __shfl_up_sync(0xffffffffu, x, o);
        if (lane >= o) x += y;
    }
    __shared__ int ws[8], wso[8];
    if (lane == 31) ws[w] = x;
    __syncthreads();
    if (t < 8) {
        int s = 0;
        for (int i = 0; i < t; i++) s += ws[i];
        wso[t] = s;
    }
    __syncthreads();
    int incl = x + wso[w];
    if (t < NN / 256) g_boff[t] = incl - v;
    if (t == 255) g_offsets[NN] = incl;
}

__global__ void blockscan_kernel() {
    int b = blockIdx.x, t = threadIdx.x, i = b * 256 + t;
    int c = g_counts[i];
    int lane = t & 31, w = t >> 5;
    int x = c;
    #pragma unroll
    for (int o = 1; o < 32; o <<= 1) {
        int y = __shfl_up_sync(0xffffffffu, x, o);
        if (lane >= o) x += y;
    }
    __shared__ int ws[8], wso[8];
    if (lane == 31) ws[w] = x;
    __syncthreads();
    if (t < 8) {
        int s = 0;
        for (int j = 0; j < t; j++) s += ws[j];
        wso[t] = s;
    }
    __syncthreads();
    g_offsets[i] = x - c + wso[w] + g_boff[b];
    g_dinv[i] = rsqrtf((float)(c + 1));
}

// scatter dst-sorted edge records {src, dinv[d]*dinv[s]} (needs g_dinv ready)
__global__ void scatter_kernel(const void* __restrict__ ei) {
    int e = blockIdx.x * blockDim.x + threadIdx.x;
    if (e < EE) {
        int d = ei_at(ei, (size_t)EE + e);
        int s = ei_at(ei, (size_t)e);
        int pos = g_offsets[d] + atomicAdd(&g_fill[d], 1);
        float w = g_dinv[d] * g_dinv[s];
        g_edge[pos] = make_int2(s, __float_as_int(w));
    }
}

// -------------------- x -> fp16 --------------------
__global__ void xconv_kernel(const float* __restrict__ x) {
    int i = blockIdx.x * blockDim.x + threadIdx.x;  // over NN*F_IN/2
    if (i < NN * F_IN / 2) {
        float2 v = ((const float2*)x)[i];
        ((__half2*)g_hf)[i] = __floats2half2_rn(v.x, v.y);
    }
}

// -------------------- all weight splits in one kernel ------------------------
#define W1SZ (F_IN * H1)
#define W2SZ (H1 * H2)
#define W3SZ (H2 * H3)
__global__ void splitw_all(const float* __restrict__ W1,
                           const float* __restrict__ W2,
                           const float* __restrict__ W3) {
    int i = blockIdx.x * blockDim.x + threadIdx.x;
    float v;
    __half* dh;
    __half* dl;
    int j;
    if (i < W1SZ) {
        j = i; v = W1[j]; dh = g_w1H; dl = g_w1L;
    } else if (i < W1SZ + W2SZ) {
        j = i - W1SZ; v = W2[j]; dh = g_w2H; dl = g_w2L;
    } else if (i < W1SZ + W2SZ + W3SZ) {
        j = i - W1SZ - W2SZ; v = W3[j]; dh = g_w3H; dl = g_w3L;
    } else return;
    __half h = __float2half_rn(v);
    dh[j] = h;
    dl[j] = __float2half_rn(v - __half2float(h));
}

// -------------------- agg1: fp16 x (H=128) -> fp16 output --------------------
__global__ void agg1_kernel() {
    int gw = (blockIdx.x * blockDim.x + threadIdx.x) >> 5;
    int lane = threadIdx.x & 31;
    if (gw >= NN) return;
    const int n = gw;
    const float dd = g_dinv[n];
    const float w0 = dd * dd;

    float acc[4];
    {
        uint2 hv = ((const uint2*)(g_hf + (size_t)n * F_IN))[lane];
        float2 f0 = h2f2(hv.x), f1 = h2f2(hv.y);
        acc[0] = w0 * f0.x; acc[1] = w0 * f0.y;
        acc[2] = w0 * f1.x; acc[3] = w0 * f1.y;
    }

    const int e0 = g_offsets[n], e1 = g_offsets[n + 1];
    for (int e = e0; e < e1; e++) {
        int2 ew = g_edge[e];
        float w = __int_as_float(ew.y);
        uint2 hv = ((const uint2*)(g_hf + (size_t)ew.x * F_IN))[lane];
        float2 f0 = h2f2(hv.x), f1 = h2f2(hv.y);
        acc[0] += w * f0.x; acc[1] += w * f0.y;
        acc[2] += w * f1.x; acc[3] += w * f1.y;
    }

    __half2 o0 = __floats2half2_rn(acc[0], acc[1]);
    __half2 o1 = __floats2half2_rn(acc[2], acc[3]);
    ((uint2*)(g_af + (size_t)n * F_IN))[lane] =
        make_uint2(*(uint32_t*)&o0, *(uint32_t*)&o1);
}

// -------------------- agg23: fp16 input (H=256) -> fp16 output ---------------
__global__ void agg23_kernel() {
    int gw = (blockIdx.x * blockDim.x + threadIdx.x) >> 5;
    int lane = threadIdx.x & 31;
    if (gw >= NN) return;
    const int n = gw;
    const float dd = g_dinv[n];
    const float w0 = dd * dd;

    float acc[8];
    {
        uint4 hv = ((const uint4*)(g_hf + (size_t)n * 256))[lane];
        float2 f0 = h2f2(hv.x), f1 = h2f2(hv.y), f2 = h2f2(hv.z), f3 = h2f2(hv.w);
        acc[0] = w0 * f0.x; acc[1] = w0 * f0.y; acc[2] = w0 * f1.x; acc[3] = w0 * f1.y;
        acc[4] = w0 * f2.x; acc[5] = w0 * f2.y; acc[6] = w0 * f3.x; acc[7] = w0 * f3.y;
    }

    const int e0 = g_offsets[n], e1 = g_offsets[n + 1];
    for (int e = e0; e < e1; e++) {
        int2 ew = g_edge[e];
        float w = __int_as_float(ew.y);
        uint4 hv = ((const uint4*)(g_hf + (size_t)ew.x * 256))[lane];
        float2 f0 = h2f2(hv.x), f1 = h2f2(hv.y), f2 = h2f2(hv.z), f3 = h2f2(hv.w);
        acc[0] += w * f0.x; acc[1] += w * f0.y; acc[2] += w * f1.x; acc[3] += w * f1.y;
        acc[4] += w * f2.x; acc[5] += w * f2.y; acc[6] += w * f3.x; acc[7] += w * f3.y;
    }

    __half2 o0 = __floats2half2_rn(acc[0], acc[1]);
    __half2 o1 = __floats2half2_rn(acc[2], acc[3]);
    __half2 o2 = __floats2half2_rn(acc[4], acc[5]);
    __half2 o3 = __floats2half2_rn(acc[6], acc[7]);
    uint4 ov;
    ov.x = *(uint32_t*)&o0; ov.y = *(uint32_t*)&o1;
    ov.z = *(uint32_t*)&o2; ov.w = *(uint32_t*)&o3;
    ((uint4*)(g_af + (size_t)n * 256))[lane] = ov;
}

// -------------------- GEMM via mma.sync fp16, 3-stage cp.async, occ 2 --------
// CTA tile 128x128, 8 warps (4x2), warp tile 32x64, k-chunk 32, 3-stage ring.
// A = single fp16 (g_af), W = fp16 hi + residual (WSEL) -> 2 MMA terms.
// Epilogue: tanh(acc + bias) -> fp16 into g_hf (all layers; FC reads fp16 h3).
#define A_PITCH 80    // 32 fp16 = 64B + 16B pad
#define B_PITCH 272   // 128 fp16 = 256B + 16B pad
#define SM_A  0
#define SM_BH (128 * A_PITCH)
#define SM_BL (128 * A_PITCH + 32 * B_PITCH)
#define SM_STG (128 * A_PITCH + 2 * 32 * B_PITCH)   // 27648 B
#define SM_TOT (3 * SM_STG)                         // 82944 B

template <int K, int NB, int WSEL>
__device__ __forceinline__ void gemm_load_chunk(uint32_t sb, int stg, int m0, int n0,
                                                int k0, int t) {
    uint32_t base = sb + stg * SM_STG;
    const __half* wH = wselH(WSEL);
    const __half* wL = wselL(WSEL);
    #pragma unroll
    for (int i = 0; i < 2; i++) {
        int idx = t + i * 256;
        int row = idx >> 2, seg = idx & 3;
        size_t gofs = ((size_t)(m0 + row) * K + k0) * 2 + seg * 16;
        cpa16(base + SM_A + row * A_PITCH + seg * 16, (const char*)g_af + gofs);
    }
    #pragma unroll
    for (int i = 0; i < 2; i++) {
        int idx = t + i * 256;
        int row = idx >> 4, seg = idx & 15;
        size_t gofs = ((size_t)(k0 + row) * NB + n0) * 2 + seg * 16;
        cpa16(base + SM_BH + row * B_PITCH + seg * 16, (const char*)wH + gofs);
        cpa16(base + SM_BL + row * B_PITCH + seg * 16, (const char*)wL + gofs);
    }
    CPA_COMMIT();
}

template <int K, int NB, int WSEL>
__global__ void __launch_bounds__(256, 2)
gemm_mma(const float* __restrict__ bias) {
    extern __shared__ char sm[];
    const uint32_t sb = smem_u32(sm);
    const int t = threadIdx.x;
    const int warp = t >> 5, lane = t & 31;
    const int wm = warp >> 1, wn = warp & 1;
    const int m0 = blockIdx.y * 128, n0 = blockIdx.x * 128;
    constexpr int NCH = K / 32;

    float c[2][8][4];
    #pragma unroll
    for (int i = 0; i < 2; i++)
        #pragma unroll
        for (int j = 0; j < 8; j++)
            #pragma unroll
            for (int q = 0; q < 4; q++) c[i][j][q] = 0.0f;

    gemm_load_chunk<K, NB, WSEL>(sb, 0, m0, n0, 0, t);
    gemm_load_chunk<K, NB, WSEL>(sb, 1, m0, n0, 32, t);

    for (int ch = 0; ch < NCH; ch++) {
        if (ch + 1 < NCH) { CPA_WAIT1(); } else { CPA_WAIT0(); }
        __syncthreads();
        if (ch + 2 < NCH)
            gemm_load_chunk<K, NB, WSEL>(sb, (ch + 2) % 3, m0, n0, (ch + 2) * 32, t);

        const char* base = sm + (ch % 3) * SM_STG;
        #pragma unroll
        for (int k16 = 0; k16 < 2; k16++) {
            uint32_t aa[2][4];
            #pragma unroll
            for (int mt = 0; mt < 2; mt++) {
                int row = wm * 32 + mt * 16 + (lane & 15);
                int cb = k16 * 32 + ((lane >> 4) << 4);
                LDSM_X4(aa[mt], smem_u32(base + SM_A + row * A_PITCH + cb));
            }
            uint32_t bh[4][4], bl[4][4];
            #pragma unroll
            for (int np = 0; np < 4; np++) {
                int krow = k16 * 16 + (lane & 7) + (lane & 8);
                int cb = wn * 128 + np * 32 + ((lane >> 4) << 4);
                LDSM_X4T(bh[np], smem_u32(base + SM_BH + krow * B_PITCH + cb));
                LDSM_X4T(bl[np], smem_u32(base + SM_BL + krow * B_PITCH + cb));
            }
            #pragma unroll
            for (int mt = 0; mt < 2; mt++) {
                #pragma unroll
                for (int np = 0; np < 4; np++) {
                    mma16816h(c[mt][np * 2],     aa[mt], bh[np][0], bh[np][1]);
                    mma16816h(c[mt][np * 2],     aa[mt], bl[np][0], bl[np][1]);
                    mma16816h(c[mt][np * 2 + 1], aa[mt], bh[np][2], bh[np][3]);
                    mma16816h(c[mt][np * 2 + 1], aa[mt], bl[np][2], bl[np][3]);
                }
            }
        }
        __syncthreads();
    }

    // epilogue: tanh(acc + bias) -> fp16 into g_hf
    const int g = lane >> 2, tq = lane & 3;
    #pragma unroll
    for (int mt = 0; mt < 2; mt++) {
        int row = m0 + wm * 32 + mt * 16 + g;
        #pragma unroll
        for (int n8 = 0; n8 < 8; n8++) {
            int col = n0 + wn * 64 + n8 * 8 + 2 * tq;
            float b0 = __ldg(bias + col), b1 = __ldg(bias + col + 1);
            float v0 = tanhf(c[mt][n8][0] + b0);
            float v1 = tanhf(c[mt][n8][1] + b1);
            float v2 = tanhf(c[mt][n8][2] + b0);
            float v3 = tanhf(c[mt][n8][3] + b1);
            *(__half2*)(g_hf + (size_t)row * NB + col) = __floats2half2_rn(v0, v1);
            *(__half2*)(g_hf + (size_t)(row + 8) * NB + col) = __floats2half2_rn(v2, v3);
        }
    }
}

// -------------------- final FC: out[64,64] = h3.reshape(64,128000) @ Wfc + bfc
__global__ void fc_init(const float* __restrict__ bfc, float* __restrict__ out) {
    int i = blockIdx.x * blockDim.x + threadIdx.x;
    if (i < NG * OUTD) out[i] = bfc[i & 63];
}

#define FC_KCH 256
__global__ void fc_kernel(const float* __restrict__ Wfc,
                          float* __restrict__ out) {
    const __half* __restrict__ h3 = g_hf;   // fp16 h3 after layer-3 GEMM
    __shared__ float Ws[16][64];
    __shared__ float Hs[64][17];
    const int t = threadIdx.x;
    const int tg = t & 15;
    const int to = t >> 4;
    unsigned long long accp[4][2];   // packed f32x2 accumulators
    #pragma unroll
    for (int i = 0; i < 4; i++) {
        accp[i][0] = 0ull;
        accp[i][1] = 0ull;
    }

    const int kbase = blockIdx.x * FC_KCH;
    for (int kk0 = 0; kk0 < FC_KCH; kk0 += 16) {
        const int k0 = kbase + kk0;
        #pragma unroll
        for (int rr = 0; rr < 4; rr++) {
            int idx = t + rr * 256;
            int kr = idx >> 6, nn = idx & 63;
            Ws[kr][nn] = Wfc[(size_t)(k0 + kr) * OUTD + nn];
        }
        #pragma unroll
        for (int rr = 0; rr < 4; rr++) {
            int idx = t + rr * 256;
            int g = idx >> 4, kk = idx & 15;
            Hs[g][kk] = __half2float(h3[(size_t)g * 128000 + k0 + kk]);
        }
        __syncthreads();
        #pragma unroll
        for (int kk = 0; kk < 16; kk++) {
            unsigned long long wvp[2];
            wvp[0] = pack2(Ws[kk][4 * to + 0], Ws[kk][4 * to + 1]);
            wvp[1] = pack2(Ws[kk][4 * to + 2], Ws[kk][4 * to + 3]);
            #pragma unroll
            for (int i = 0; i < 4; i++) {
                float hv = Hs[4 * tg + i][kk];
                unsigned long long hp = pack2(hv, hv);
                FFMA2(accp[i][0], hp, wvp[0]);
                FFMA2(accp[i][1], hp, wvp[1]);
            }
        }
        __syncthreads();
    }
    #pragma unroll
    for (int i = 0; i < 4; i++) {
        float a0, a1, a2, a3;
        unpack2(accp[i][0], a0, a1);
        unpack2(accp[i][1], a2, a3);
        float* op = &out[(4 * tg + i) * OUTD + 4 * to];
        atomicAdd(op + 0, a0);
        atomicAdd(op + 1, a1);
        atomicAdd(op + 2, a2);
        atomicAdd(op + 3, a3);
    }
}

// -------------------- launch --------------------
extern "C" void kernel_launch(void* const* d_in, const int* in_sizes, int n_in,
                              void* d_out, int out_size) {
    const float* x   = (const float*)d_in[0];
    const void*  ei  = d_in[1];
    const float* W1  = (const float*)d_in[3];
    const float* b1  = (const float*)d_in[4];
    const float* W2  = (const float*)d_in[5];
    const float* b2  = (const float*)d_in[6];
    const float* W3  = (const float*)d_in[7];
    const float* b3  = (const float*)d_in[8];
    const float* Wfc = (const float*)d_in[9];
    const float* bfc = (const float*)d_in[10];
    float* out = (float*)d_out;

    cudaFuncSetAttribute(gemm_mma<F_IN, H1, 1>, cudaFuncAttributeMaxDynamicSharedMemorySize, SM_TOT);
    cudaFuncSetAttribute(gemm_mma<H1, H2, 2>,   cudaFuncAttributeMaxDynamicSharedMemorySize, SM_TOT);
    cudaFuncSetAttribute(gemm_mma<H2, H3, 3>,   cudaFuncAttributeMaxDynamicSharedMemorySize, SM_TOT);

    // preprocessing (single stream; graph-capture-safe)
    zero_kernel<<<(NN / 4 + 255) / 256, 256>>>(ei);
    hist_kernel<<<EE / 256, 256>>>(ei);
    reduce_kernel<<<NN / 256, 256>>>();
    scanpart_kernel<<<1, 256>>>();
    blockscan_kernel<<<NN / 256, 256>>>();
    scatter_kernel<<<EE / 256, 256>>>(ei);
    xconv_kernel<<<(NN * F_IN / 2 + 255) / 256, 256>>>(x);
    splitw_all<<<(W1SZ + W2SZ + W3SZ + 255) / 256, 256>>>(W1, W2, W3);
    fc_init<<<(NG * OUTD + 255) / 256, 256>>>(bfc, out);

    const int aggBlocks = (NN * 32) / 256;

    // layer 1: agg-first (Â x, fp16 gather) then GEMM(128->256), tanh -> fp16
    agg1_kernel<<<aggBlocks, 256>>>();
    gemm_mma<F_IN, H1, 1><<<dim3(H1 / 128, NN / 128), 256, SM_TOT>>>(b1);

    // layer 2: agg (fp16 gather, 256) then GEMM(256->256), tanh -> fp16
    agg23_kernel<<<aggBlocks, 256>>>();
    gemm_mma<H1, H2, 2><<<dim3(H2 / 128, NN / 128), 256, SM_TOT>>>(b2);

    // layer 3: agg then GEMM(256->128), tanh -> fp16 h3
    agg23_kernel<<<aggBlocks, 256>>>();
    gemm_mma<H2, H3, 3><<<dim3(H3 / 128, NN / 128), 256, SM_TOT>>>(b3);

    // final FC (fp16 h3, FFMA2) with split-K atomics
    fc_kernel<<<128000 / FC_KCH, 256>>>(Wfc, out);
}

// round 16
// speedup vs baseline: 1.6915x; 1.0367x over previous
#include <cuda_runtime.h>
#include <cuda_bf16.h>
#include <cuda_fp16.h>
#include <cstdint>
#include <cstddef>

// Problem constants (fixed by the dataset)
#define NN 64000
#define EE 1048576
#define NG 64
#define NBN 1000
#define F_IN 128
#define H1 256
#define H2 256
#define H3 128
#define OUTD 64

// -------------------- scratch (device globals; no allocs) --------------------
__device__ __align__(16) __half g_af[(size_t)NN * 256];    // fp16 GEMM-A / raw t3
__device__ __align__(16) __half g_hf[(size_t)NN * 256];    // fp16 activations / h3
__device__ __align__(16) __half g_w1H[F_IN * H1], g_w1L[F_IN * H1];
__device__ __align__(16) __half g_w2H[H1 * H2],  g_w2L[H1 * H2];
__device__ __align__(16) __half g_w3H[H2 * H3],  g_w3L[H2 * H3];
__device__ int2  g_edge[EE];                               // {src, w = dinv[d]*dinv[s]}
__device__ __align__(16) int g_counts[NN];
__device__ int   g_offsets[NN + 1];
__device__ __align__(16) int g_fill[NN];
__device__ float g_dinv[NN];
__device__ int   g_isI64;
__device__ int   g_bsum[256];
__device__ int   g_boff[256];

__device__ __forceinline__ int ei_at(const void* ei, size_t idx) {
    if (g_isI64) return (int)((const long long*)ei)[idx];
    return ((const int*)ei)[idx];
}

// weight-buffer selector (device-side only)
__device__ __forceinline__ const __half* wselH(int s) {
    return s == 1 ? g_w1H : (s == 2 ? g_w2H : g_w3H);
}
__device__ __forceinline__ const __half* wselL(int s) {
    return s == 1 ? g_w1L : (s == 2 ? g_w2L : g_w3L);
}

// -------------------- PTX helpers (family-generic sm_80+ features only) ------
__device__ __forceinline__ uint32_t smem_u32(const void* p) {
    uint32_t a;
    asm("{ .reg .u64 t; cvta.to.shared.u64 t, %1; cvt.u32.u64 %0, t; }" : "=r"(a) : "l"(p));
    return a;
}
__device__ __forceinline__ void cpa16(uint32_t s, const void* g) {
    asm volatile("cp.async.cg.shared.global [%0], [%1], 16;" :: "r"(s), "l"(g) : "memory");
}
#define CPA_COMMIT() asm volatile("cp.async.commit_group;" ::: "memory")
#define CPA_WAIT0()  asm volatile("cp.async.wait_group 0;" ::: "memory")
#define CPA_WAIT1()  asm volatile("cp.async.wait_group 1;" ::: "memory")

#define LDSM_X4(r, a)                                                              \
    asm volatile("ldmatrix.sync.aligned.m8n8.x4.shared.b16 {%0,%1,%2,%3}, [%4];"   \
                 : "=r"((r)[0]), "=r"((r)[1]), "=r"((r)[2]), "=r"((r)[3]) : "r"(a))
#define LDSM_X4T(r, a)                                                                  \
    asm volatile("ldmatrix.sync.aligned.m8n8.x4.trans.shared.b16 {%0,%1,%2,%3}, [%4];"  \
                 : "=r"((r)[0]), "=r"((r)[1]), "=r"((r)[2]), "=r"((r)[3]) : "r"(a))

__device__ __forceinline__ void mma16816h(float* c, const uint32_t* a,
                                          uint32_t b0, uint32_t b1) {
    asm volatile(
        "mma.sync.aligned.m16n8k16.row.col.f32.f16.f16.f32 "
        "{%0,%1,%2,%3}, {%4,%5,%6,%7}, {%8,%9}, {%0,%1,%2,%3};"
        : "+f"(c[0]), "+f"(c[1]), "+f"(c[2]), "+f"(c[3])
        : "r"(a[0]), "r"(a[1]), "r"(a[2]), "r"(a[3]), "r"(b0), "r"(b1));
}

__device__ __forceinline__ float2 h2f2(uint32_t u) {
    return __half22float2(*(__half2*)&u);
}

// packed f32x2 helpers (FFMA2 only reachable via PTX)
__device__ __forceinline__ unsigned long long pack2(float x, float y) {
    unsigned long long r;
    asm("mov.b64 %0, {%1, %2};" : "=l"(r) : "f"(x), "f"(y));
    return r;
}
__device__ __forceinline__ void unpack2(unsigned long long p, float& x, float& y) {
    asm("mov.b64 {%0, %1}, %2;" : "=f"(x), "=f"(y) : "l"(p));
}
#define FFMA2(acc, ap, bp) \
    asm("fma.rn.f32x2 %0, %1, %2, %0;" : "+l"(acc) : "l"(ap), "l"(bp))

// -------------------- preprocessing --------------------
// zero + dtype detection fused (detect by block 0 thread 0; hist runs after)
__global__ void zero_kernel(const void* ei) {
    int i = blockIdx.x * blockDim.x + threadIdx.x;   // over NN/4
    if (i < NN / 4) {
        ((int4*)g_counts)[i] = make_int4(0, 0, 0, 0);
        ((int4*)g_fill)[i] = make_int4(0, 0, 0, 0);
    }
    if (blockIdx.x == 0 && threadIdx.x == 0) {
        const unsigned int* w = (const unsigned int*)ei;
        int is64 = 1;
        #pragma unroll
        for (int k = 0; k < 32; k++)
            if (w[2 * k + 1] != 0u) is64 = 0;
        g_isI64 = is64;
    }
}

__global__ void hist_kernel(const void* __restrict__ ei) {
    int e = blockIdx.x * blockDim.x + threadIdx.x;
    if (e < EE) {
        int d = ei_at(ei, (size_t)EE + e);
        atomicAdd(&g_counts[d], 1);
    }
}

__global__ void reduce_kernel() {
    int b = blockIdx.x;
    int v = g_counts[b * 256 + threadIdx.x];
    #pragma unroll
    for (int o = 16; o; o >>= 1) v += __shfl_down_sync(0xffffffffu, v, o);
    __shared__ int ws[8];
    if ((threadIdx.x & 31) == 0) ws[threadIdx.x >> 5] = v;
    __syncthreads();
    if (threadIdx.x == 0) {
        int s = 0;
        #pragma unroll
        for (int i = 0; i < 8; i++) s += ws[i];
        g_bsum[b] = s;
    }
}

__global__ void scanpart_kernel() {
    int t = threadIdx.x;
    int v = (t < NN / 256) ? g_bsum[t] : 0;
    int lane = t & 31, w = t >> 5;
    int x = v;
    #pragma unroll
    for (int o = 1; o < 32; o <<= 1) {
        int y = __shfl_up_sync(0xffffffffu, x, o);
        if (lane >= o) x += y;
    }
    __shared__ int ws[8], wso[8];
    if (lane == 31) ws[w] = x;
    __syncthreads();
    if (t < 8) {
        int s = 0;
        for (int i = 0; i < t; i++) s += ws[i];
        wso[t] = s;
    }
    __syncthreads();
    int incl = x + wso[w];
    if (t < NN / 256) g_boff[t] = incl - v;
    if (t == 255) g_offsets[NN] = incl;
}

__global__ void blockscan_kernel() {
    int b = blockIdx.x, t = threadIdx.x, i = b * 256 + t;
    int c = g_counts[i];
    int lane = t & 31, w = t >> 5;
    int x = c;
    #pragma unroll
    for (int o = 1; o < 32; o <<= 1) {
        int y = __shfl_up_sync(0xffffffffu, x, o);
        if (lane >= o) x += y;
    }
    __shared__ int ws[8], wso[8];
    if (lane == 31) ws[w] = x;
    __syncthreads();
    if (t < 8) {
        int s = 0;
        for (int j = 0; j < t; j++) s += ws[j];
        wso[t] = s;
    }
    __syncthreads();
    g_offsets[i] = x - c + wso[w] + g_boff[b];
    g_dinv[i] = rsqrtf((float)(c + 1));
}

// scatter dst-sorted edge records {src, dinv[d]*dinv[s]} (needs g_dinv ready)
__global__ void scatter_kernel(const void* __restrict__ ei) {
    int e = blockIdx.x * blockDim.x + threadIdx.x;
    if (e < EE) {
        int d = ei_at(ei, (size_t)EE + e);
        int s = ei_at(ei, (size_t)e);
        int pos = g_offsets[d] + atomicAdd(&g_fill[d], 1);
        float w = g_dinv[d] * g_dinv[s];
        g_edge[pos] = make_int2(s, __float_as_int(w));
    }
}

// -------------------- x -> fp16 --------------------
__global__ void xconv_kernel(const float* __restrict__ x) {
    int i = blockIdx.x * blockDim.x + threadIdx.x;  // over NN*F_IN/2
    if (i < NN * F_IN / 2) {
        float2 v = ((const float2*)x)[i];
        ((__half2*)g_hf)[i] = __floats2half2_rn(v.x, v.y);
    }
}

// -------------------- all weight splits in one kernel ------------------------
#define W1SZ (F_IN * H1)
#define W2SZ (H1 * H2)
#define W3SZ (H2 * H3)
__global__ void splitw_all(const float* __restrict__ W1,
                           const float* __restrict__ W2,
                           const float* __restrict__ W3) {
    int i = blockIdx.x * blockDim.x + threadIdx.x;
    float v;
    __half* dh;
    __half* dl;
    int j;
    if (i < W1SZ) {
        j = i; v = W1[j]; dh = g_w1H; dl = g_w1L;
    } else if (i < W1SZ + W2SZ) {
        j = i - W1SZ; v = W2[j]; dh = g_w2H; dl = g_w2L;
    } else if (i < W1SZ + W2SZ + W3SZ) {
        j = i - W1SZ - W2SZ; v = W3[j]; dh = g_w3H; dl = g_w3L;
    } else return;
    __half h = __float2half_rn(v);
    dh[j] = h;
    dl[j] = __float2half_rn(v - __half2float(h));
}

// -------------------- agg1: fp16 x (H=128, g_hf) -> fp16 g_af ----------------
__global__ void agg1_kernel() {
    int gw = (blockIdx.x * blockDim.x + threadIdx.x) >> 5;
    int lane = threadIdx.x & 31;
    if (gw >= NN) return;
    const int n = gw;
    const float dd = g_dinv[n];
    const float w0 = dd * dd;

    float acc[4];
    {
        uint2 hv = ((const uint2*)(g_hf + (size_t)n * F_IN))[lane];
        float2 f0 = h2f2(hv.x), f1 = h2f2(hv.y);
        acc[0] = w0 * f0.x; acc[1] = w0 * f0.y;
        acc[2] = w0 * f1.x; acc[3] = w0 * f1.y;
    }

    const int e0 = g_offsets[n], e1 = g_offsets[n + 1];
    for (int e = e0; e < e1; e++) {
        int2 ew = g_edge[e];
        float w = __int_as_float(ew.y);
        uint2 hv = ((const uint2*)(g_hf + (size_t)ew.x * F_IN))[lane];
        float2 f0 = h2f2(hv.x), f1 = h2f2(hv.y);
        acc[0] += w * f0.x; acc[1] += w * f0.y;
        acc[2] += w * f1.x; acc[3] += w * f1.y;
    }

    __half2 o0 = __floats2half2_rn(acc[0], acc[1]);
    __half2 o1 = __floats2half2_rn(acc[2], acc[3]);
    ((uint2*)(g_af + (size_t)n * F_IN))[lane] =
        make_uint2(*(uint32_t*)&o0, *(uint32_t*)&o1);
}

// -------------------- agg2: fp16 (H=256, g_hf) -> fp16 g_af ------------------
__global__ void agg23_kernel() {
    int gw = (blockIdx.x * blockDim.x + threadIdx.x) >> 5;
    int lane = threadIdx.x & 31;
    if (gw >= NN) return;
    const int n = gw;
    const float dd = g_dinv[n];
    const float w0 = dd * dd;

    float acc[8];
    {
        uint4 hv = ((const uint4*)(g_hf + (size_t)n * 256))[lane];
        float2 f0 = h2f2(hv.x), f1 = h2f2(hv.y), f2 = h2f2(hv.z), f3 = h2f2(hv.w);
        acc[0] = w0 * f0.x; acc[1] = w0 * f0.y; acc[2] = w0 * f1.x; acc[3] = w0 * f1.y;
        acc[4] = w0 * f2.x; acc[5] = w0 * f2.y; acc[6] = w0 * f3.x; acc[7] = w0 * f3.y;
    }

    const int e0 = g_offsets[n], e1 = g_offsets[n + 1];
    for (int e = e0; e < e1; e++) {
        int2 ew = g_edge[e];
        float w = __int_as_float(ew.y);
        uint4 hv = ((const uint4*)(g_hf + (size_t)ew.x * 256))[lane];
        float2 f0 = h2f2(hv.x), f1 = h2f2(hv.y), f2 = h2f2(hv.z), f3 = h2f2(hv.w);
        acc[0] += w * f0.x; acc[1] += w * f0.y; acc[2] += w * f1.x; acc[3] += w * f1.y;
        acc[4] += w * f2.x; acc[5] += w * f2.y; acc[6] += w * f3.x; acc[7] += w * f3.y;
    }

    __half2 o0 = __floats2half2_rn(acc[0], acc[1]);
    __half2 o1 = __floats2half2_rn(acc[2], acc[3]);
    __half2 o2 = __floats2half2_rn(acc[4], acc[5]);
    __half2 o3 = __floats2half2_rn(acc[6], acc[7]);
    uint4 ov;
    ov.x = *(uint32_t*)&o0; ov.y = *(uint32_t*)&o1;
    ov.z = *(uint32_t*)&o2; ov.w = *(uint32_t*)&o3;
    ((uint4*)(g_af + (size_t)n * 256))[lane] = ov;
}

// -------- agg3: raw t3 (H=128, g_af) -> h3 = tanh(agg + b3) in g_hf ----------
__global__ void aggtanh_kernel(const float* __restrict__ bias) {
    int gw = (blockIdx.x * blockDim.x + threadIdx.x) >> 5;
    int lane = threadIdx.x & 31;
    if (gw >= NN) return;
    const int n = gw;
    const float dd = g_dinv[n];
    const float w0 = dd * dd;

    float acc[4];
    {
        uint2 hv = ((const uint2*)(g_af + (size_t)n * H3))[lane];
        float2 f0 = h2f2(hv.x), f1 = h2f2(hv.y);
        acc[0] = w0 * f0.x; acc[1] = w0 * f0.y;
        acc[2] = w0 * f1.x; acc[3] = w0 * f1.y;
    }

    const int e0 = g_offsets[n], e1 = g_offsets[n + 1];
    for (int e = e0; e < e1; e++) {
        int2 ew = g_edge[e];
        float w = __int_as_float(ew.y);
        uint2 hv = ((const uint2*)(g_af + (size_t)ew.x * H3))[lane];
        float2 f0 = h2f2(hv.x), f1 = h2f2(hv.y);
        acc[0] += w * f0.x; acc[1] += w * f0.y;
        acc[2] += w * f1.x; acc[3] += w * f1.y;
    }

    float4 b = ((const float4*)bias)[lane];
    float v0 = tanhf(acc[0] + b.x);
    float v1 = tanhf(acc[1] + b.y);
    float v2 = tanhf(acc[2] + b.z);
    float v3 = tanhf(acc[3] + b.w);
    __half2 o0 = __floats2half2_rn(v0, v1);
    __half2 o1 = __floats2half2_rn(v2, v3);
    ((uint2*)(g_hf + (size_t)n * H3))[lane] =
        make_uint2(*(uint32_t*)&o0, *(uint32_t*)&o1);
}

// -------------------- GEMM via mma.sync fp16, 3-stage cp.async, occ 2 --------
// CTA tile 128x128, 8 warps (4x2), warp tile 32x64, k-chunk 32, 3-stage ring.
// A = single fp16 (ASRC: 0=g_af, 1=g_hf); W = fp16 hi + residual (WSEL).
// Epilogue: TANH ? tanh(acc+bias)->g_hf : raw acc (fp16) -> g_af.
#define A_PITCH 80    // 32 fp16 = 64B + 16B pad
#define B_PITCH 272   // 128 fp16 = 256B + 16B pad
#define SM_A  0
#define SM_BH (128 * A_PITCH)
#define SM_BL (128 * A_PITCH + 32 * B_PITCH)
#define SM_STG (128 * A_PITCH + 2 * 32 * B_PITCH)   // 27648 B
#define SM_TOT (3 * SM_STG)                         // 82944 B

template <int K, int NB, int WSEL, int ASRC>
__device__ __forceinline__ void gemm_load_chunk(uint32_t sb, int stg, int m0, int n0,
                                                int k0, int t) {
    uint32_t base = sb + stg * SM_STG;
    const __half* A = ASRC ? g_hf : g_af;
    const __half* wH = wselH(WSEL);
    const __half* wL = wselL(WSEL);
    #pragma unroll
    for (int i = 0; i < 2; i++) {
        int idx = t + i * 256;
        int row = idx >> 2, seg = idx & 3;
        size_t gofs = ((size_t)(m0 + row) * K + k0) * 2 + seg * 16;
        cpa16(base + SM_A + row * A_PITCH + seg * 16, (const char*)A + gofs);
    }
    #pragma unroll
    for (int i = 0; i < 2; i++) {
        int idx = t + i * 256;
        int row = idx >> 4, seg = idx & 15;
        size_t gofs = ((size_t)(k0 + row) * NB + n0) * 2 + seg * 16;
        cpa16(base + SM_BH + row * B_PITCH + seg * 16, (const char*)wH + gofs);
        cpa16(base + SM_BL + row * B_PITCH + seg * 16, (const char*)wL + gofs);
    }
    CPA_COMMIT();
}

template <int K, int NB, int WSEL, int ASRC, int TANH>
__global__ void __launch_bounds__(256, 2)
gemm_mma(const float* __restrict__ bias) {
    extern __shared__ char sm[];
    const uint32_t sb = smem_u32(sm);
    const int t = threadIdx.x;
    const int warp = t >> 5, lane = t & 31;
    const int wm = warp >> 1, wn = warp & 1;
    const int m0 = blockIdx.y * 128, n0 = blockIdx.x * 128;
    constexpr int NCH = K / 32;

    float c[2][8][4];
    #pragma unroll
    for (int i = 0; i < 2; i++)
        #pragma unroll
        for (int j = 0; j < 8; j++)
            #pragma unroll
            for (int q = 0; q < 4; q++) c[i][j][q] = 0.0f;

    gemm_load_chunk<K, NB, WSEL, ASRC>(sb, 0, m0, n0, 0, t);
    gemm_load_chunk<K, NB, WSEL, ASRC>(sb, 1, m0, n0, 32, t);

    for (int ch = 0; ch < NCH; ch++) {
        if (ch + 1 < NCH) { CPA_WAIT1(); } else { CPA_WAIT0(); }
        __syncthreads();
        if (ch + 2 < NCH)
            gemm_load_chunk<K, NB, WSEL, ASRC>(sb, (ch + 2) % 3, m0, n0, (ch + 2) * 32, t);

        const char* base = sm + (ch % 3) * SM_STG;
        #pragma unroll
        for (int k16 = 0; k16 < 2; k16++) {
            uint32_t aa[2][4];
            #pragma unroll
            for (int mt = 0; mt < 2; mt++) {
                int row = wm * 32 + mt * 16 + (lane & 15);
                int cb = k16 * 32 + ((lane >> 4) << 4);
                LDSM_X4(aa[mt], smem_u32(base + SM_A + row * A_PITCH + cb));
            }
            uint32_t bh[4][4], bl[4][4];
            #pragma unroll
            for (int np = 0; np < 4; np++) {
                int krow = k16 * 16 + (lane & 7) + (lane & 8);
                int cb = wn * 128 + np * 32 + ((lane >> 4) << 4);
                LDSM_X4T(bh[np], smem_u32(base + SM_BH + krow * B_PITCH + cb));
                LDSM_X4T(bl[np], smem_u32(base + SM_BL + krow * B_PITCH + cb));
            }
            #pragma unroll
            for (int mt = 0; mt < 2; mt++) {
                #pragma unroll
                for (int np = 0; np < 4; np++) {
                    mma16816h(c[mt][np * 2],     aa[mt], bh[np][0], bh[np][1]);
                    mma16816h(c[mt][np * 2],     aa[mt], bl[np][0], bl[np][1]);
                    mma16816h(c[mt][np * 2 + 1], aa[mt], bh[np][2], bh[np][3]);
                    mma16816h(c[mt][np * 2 + 1], aa[mt], bl[np][2], bl[np][3]);
                }
            }
        }
        __syncthreads();
    }

    // epilogue: TANH -> tanh(acc+bias) into g_hf ; else raw fp16 into g_af
    const int g = lane >> 2, tq = lane & 3;
    __half* outp = TANH ? g_hf : g_af;
    #pragma unroll
    for (int mt = 0; mt < 2; mt++) {
        int row = m0 + wm * 32 + mt * 16 + g;
        #pragma unroll
        for (int n8 = 0; n8 < 8; n8++) {
            int col = n0 + wn * 64 + n8 * 8 + 2 * tq;
            float v0, v1, v2, v3;
            if (TANH) {
                float b0 = __ldg(bias + col), b1 = __ldg(bias + col + 1);
                v0 = tanhf(c[mt][n8][0] + b0);
                v1 = tanhf(c[mt][n8][1] + b1);
                v2 = tanhf(c[mt][n8][2] + b0);
                v3 = tanhf(c[mt][n8][3] + b1);
            } else {
                v0 = c[mt][n8][0]; v1 = c[mt][n8][1];
                v2 = c[mt][n8][2]; v3 = c[mt][n8][3];
            }
            *(__half2*)(outp + (size_t)row * NB + col) = __floats2half2_rn(v0, v1);
            *(__half2*)(outp + (size_t)(row + 8) * NB + col) = __floats2half2_rn(v2, v3);
        }
    }
}

// -------------------- final FC: out[64,64] = h3.reshape(64,128000) @ Wfc + bfc
__global__ void fc_init(const float* __restrict__ bfc, float* __restrict__ out) {
    int i = blockIdx.x * blockDim.x + threadIdx.x;
    if (i < NG * OUTD) out[i] = bfc[i & 63];
}

#define FC_KCH 256
__global__ void fc_kernel(const float* __restrict__ Wfc,
                          float* __restrict__ out) {
    const __half* __restrict__ h3 = g_hf;   // fp16 h3 after aggtanh
    __shared__ float Ws[16][64];
    __shared__ float Hs[64][17];
    const int t = threadIdx.x;
    const int tg = t & 15;
    const int to = t >> 4;
    unsigned long long accp[4][2];   // packed f32x2 accumulators
    #pragma unroll
    for (int i = 0; i < 4; i++) {
        accp[i][0] = 0ull;
        accp[i][1] = 0ull;
    }

    const int kbase = blockIdx.x * FC_KCH;
    for (int kk0 = 0; kk0 < FC_KCH; kk0 += 16) {
        const int k0 = kbase + kk0;
        #pragma unroll
        for (int rr = 0; rr < 4; rr++) {
            int idx = t + rr * 256;
            int kr = idx >> 6, nn = idx & 63;
            Ws[kr][nn] = Wfc[(size_t)(k0 + kr) * OUTD + nn];
        }
        #pragma unroll
        for (int rr = 0; rr < 4; rr++) {
            int idx = t + rr * 256;
            int g = idx >> 4, kk = idx & 15;
            Hs[g][kk] = __half2float(h3[(size_t)g * 128000 + k0 + kk]);
        }
        __syncthreads();
        #pragma unroll
        for (int kk = 0; kk < 16; kk++) {
            unsigned long long wvp[2];
            wvp[0] = pack2(Ws[kk][4 * to + 0], Ws[kk][4 * to + 1]);
            wvp[1] = pack2(Ws[kk][4 * to + 2], Ws[kk][4 * to + 3]);
            #pragma unroll
            for (int i = 0; i < 4; i++) {
                float hv = Hs[4 * tg + i][kk];
                unsigned long long hp = pack2(hv, hv);
                FFMA2(accp[i][0], hp, wvp[0]);
                FFMA2(accp[i][1], hp, wvp[1]);
            }
        }
        __syncthreads();
    }
    #pragma unroll
    for (int i = 0; i < 4; i++) {
        float a0, a1, a2, a3;
        unpack2(accp[i][0], a0, a1);
        unpack2(accp[i][1], a2, a3);
        float* op = &out[(4 * tg + i) * OUTD + 4 * to];
        atomicAdd(op + 0, a0);
        atomicAdd(op + 1, a1);
        atomicAdd(op + 2, a2);
        atomicAdd(op + 3, a3);
    }
}

// -------------------- launch --------------------
extern "C" void kernel_launch(void* const* d_in, const int* in_sizes, int n_in,
                              void* d_out, int out_size) {
    const float* x   = (const float*)d_in[0];
    const void*  ei  = d_in[1];
    const float* W1  = (const float*)d_in[3];
    const float* b1  = (const float*)d_in[4];
    const float* W2  = (const float*)d_in[5];
    const float* b2  = (const float*)d_in[6];
    const float* W3  = (const float*)d_in[7];
    const float* b3  = (const float*)d_in[8];
    const float* Wfc = (const float*)d_in[9];
    const float* bfc = (const float*)d_in[10];
    float* out = (float*)d_out;

    cudaFuncSetAttribute(gemm_mma<F_IN, H1, 1, 0, 1>, cudaFuncAttributeMaxDynamicSharedMemorySize, SM_TOT);
    cudaFuncSetAttribute(gemm_mma<H1, H2, 2, 0, 1>,   cudaFuncAttributeMaxDynamicSharedMemorySize, SM_TOT);
    cudaFuncSetAttribute(gemm_mma<H2, H3, 3, 1, 0>,   cudaFuncAttributeMaxDynamicSharedMemorySize, SM_TOT);

    // preprocessing (single stream; graph-capture-safe)
    zero_kernel<<<(NN / 4 + 255) / 256, 256>>>(ei);
    hist_kernel<<<EE / 256, 256>>>(ei);
    reduce_kernel<<<NN / 256, 256>>>();
    scanpart_kernel<<<1, 256>>>();
    blockscan_kernel<<<NN / 256, 256>>>();
    scatter_kernel<<<EE / 256, 256>>>(ei);
    xconv_kernel<<<(NN * F_IN / 2 + 255) / 256, 256>>>(x);
    splitw_all<<<(W1SZ + W2SZ + W3SZ + 255) / 256, 256>>>(W1, W2, W3);
    fc_init<<<(NG * OUTD + 255) / 256, 256>>>(bfc, out);

    const int aggBlocks = (NN * 32) / 256;

    // layer 1: agg-first (Â x, 128) then GEMM(128->256), tanh -> g_hf
    agg1_kernel<<<aggBlocks, 256>>>();
    gemm_mma<F_IN, H1, 1, 0, 1><<<dim3(H1 / 128, NN / 128), 256, SM_TOT>>>(b1);

    // layer 2: agg (256) then GEMM(256->256), tanh -> g_hf
    agg23_kernel<<<aggBlocks, 256>>>();
    gemm_mma<H1, H2, 2, 0, 1><<<dim3(H2 / 128, NN / 128), 256, SM_TOT>>>(b2);

    // layer 3 (agg-after): GEMM(h2: 256->128) raw -> g_af, then agg(128)+b3+tanh -> g_hf
    gemm_mma<H2, H3, 3, 1, 0><<<dim3(H3 / 128, NN / 128), 256, SM_TOT>>>(nullptr);
    aggtanh_kernel<<<aggBlocks, 256>>>(b3);

    // final FC (fp16 h3, FFMA2) with split-K atomics
    fc_kernel<<<128000 / FC_KCH, 256>>>(Wfc, out);
}

// round 17
// speedup vs baseline: 1.6981x; 1.0039x over previous
#include <cuda_runtime.h>
#include <cuda_bf16.h>
#include <cuda_fp16.h>
#include <cstdint>
#include <cstddef>

// Problem constants (fixed by the dataset)
#define NN 64000
#define EE 1048576
#define NG 64
#define NBN 1000
#define F_IN 128
#define H1 256
#define H2 256
#define H3 128
#define OUTD 64
#define NBLK (NN / 256)   // 250 scan blocks

// -------------------- scratch (device globals; no allocs) --------------------
__device__ __align__(16) __half g_af[(size_t)NN * 256];    // fp16 GEMM-A / raw t3
__device__ __align__(16) __half g_hf[(size_t)NN * 256];    // fp16 activations / h3
__device__ __align__(16) __half g_w1H[F_IN * H1], g_w1L[F_IN * H1];
__device__ __align__(16) __half g_w2H[H1 * H2],  g_w2L[H1 * H2];
__device__ __align__(16) __half g_w3H[H2 * H3],  g_w3L[H2 * H3];
__device__ int2  g_edge[EE];                               // {src, w = dinv[d]*dinv[s]}
__device__ __align__(16) int g_counts[NN];
__device__ int   g_offsets[NN + 1];
__device__ __align__(16) int g_fill[NN];
__device__ float g_dinv[NN];
__device__ int   g_isI64;
__device__ __align__(16) unsigned long long g_scanPack[NBLK + 2];  // (val<<2)|status

__device__ __forceinline__ int ei_at(const void* ei, size_t idx) {
    if (g_isI64) return (int)((const long long*)ei)[idx];
    return ((const int*)ei)[idx];
}

// weight-buffer selector (device-side only)
__device__ __forceinline__ const __half* wselH(int s) {
    return s == 1 ? g_w1H : (s == 2 ? g_w2H : g_w3H);
}
__device__ __forceinline__ const __half* wselL(int s) {
    return s == 1 ? g_w1L : (s == 2 ? g_w2L : g_w3L);
}

// -------------------- PTX helpers (family-generic sm_80+ features only) ------
__device__ __forceinline__ uint32_t smem_u32(const void* p) {
    uint32_t a;
    asm("{ .reg .u64 t; cvta.to.shared.u64 t, %1; cvt.u32.u64 %0, t; }" : "=r"(a) : "l"(p));
    return a;
}
__device__ __forceinline__ void cpa16(uint32_t s, const void* g) {
    asm volatile("cp.async.cg.shared.global [%0], [%1], 16;" :: "r"(s), "l"(g) : "memory");
}
#define CPA_COMMIT() asm volatile("cp.async.commit_group;" ::: "memory")
#define CPA_WAIT0()  asm volatile("cp.async.wait_group 0;" ::: "memory")
#define CPA_WAIT1()  asm volatile("cp.async.wait_group 1;" ::: "memory")

#define LDSM_X4(r, a)                                                              \
    asm volatile("ldmatrix.sync.aligned.m8n8.x4.shared.b16 {%0,%1,%2,%3}, [%4];"   \
                 : "=r"((r)[0]), "=r"((r)[1]), "=r"((r)[2]), "=r"((r)[3]) : "r"(a))
#define LDSM_X4T(r, a)                                                                  \
    asm volatile("ldmatrix.sync.aligned.m8n8.x4.trans.shared.b16 {%0,%1,%2,%3}, [%4];"  \
                 : "=r"((r)[0]), "=r"((r)[1]), "=r"((r)[2]), "=r"((r)[3]) : "r"(a))

__device__ __forceinline__ void mma16816h(float* c, const uint32_t* a,
                                          uint32_t b0, uint32_t b1) {
    asm volatile(
        "mma.sync.aligned.m16n8k16.row.col.f32.f16.f16.f32 "
        "{%0,%1,%2,%3}, {%4,%5,%6,%7}, {%8,%9}, {%0,%1,%2,%3};"
        : "+f"(c[0]), "+f"(c[1]), "+f"(c[2]), "+f"(c[3])
        : "r"(a[0]), "r"(a[1]), "r"(a[2]), "r"(a[3]), "r"(b0), "r"(b1));
}

__device__ __forceinline__ float2 h2f2(uint32_t u) {
    return __half22float2(*(__half2*)&u);
}

// packed f32x2 helpers (FFMA2 only reachable via PTX)
__device__ __forceinline__ unsigned long long pack2(float x, float y) {
    unsigned long long r;
    asm("mov.b64 %0, {%1, %2};" : "=l"(r) : "f"(x), "f"(y));
    return r;
}
__device__ __forceinline__ void unpack2(unsigned long long p, float& x, float& y) {
    asm("mov.b64 {%0, %1}, %2;" : "=f"(x), "=f"(y) : "l"(p));
}
#define FFMA2(acc, ap, bp) \
    asm("fma.rn.f32x2 %0, %1, %2, %0;" : "+l"(acc) : "l"(ap), "l"(bp))

// -------------------- preprocessing --------------------
// zero + dtype detection fused; also preset g_offsets[NN] = EE and scan status
__global__ void zero_kernel(const void* ei) {
    int i = blockIdx.x * blockDim.x + threadIdx.x;   // over NN/4
    if (i < NN / 4) {
        ((int4*)g_counts)[i] = make_int4(0, 0, 0, 0);
        ((int4*)g_fill)[i] = make_int4(0, 0, 0, 0);
    }
    if (i < NBLK + 2) g_scanPack[i] = 0ull;
    if (blockIdx.x == 0 && threadIdx.x == 0) {
        g_offsets[NN] = EE;
        const unsigned int* w = (const unsigned int*)ei;
        int is64 = 1;
        #pragma unroll
        for (int k = 0; k < 32; k++)
            if (w[2 * k + 1] != 0u) is64 = 0;
        g_isI64 = is64;
    }
}

__global__ void hist_kernel(const void* __restrict__ ei) {
    int e = blockIdx.x * blockDim.x + threadIdx.x;
    if (e < EE) {
        int d = ei_at(ei, (size_t)EE + e);
        atomicAdd(&g_counts[d], 1);
    }
}

// single-pass scan over counts -> offsets + dinv (decoupled lookback)
__global__ void scan_kernel() {
    const int bid = blockIdx.x, t = threadIdx.x;
    const int i = bid * 256 + t;
    const int c = g_counts[i];
    const int lane = t & 31, w = t >> 5;

    // block-local inclusive scan
    int x = c;
    #pragma unroll
    for (int o = 1; o < 32; o <<= 1) {
        int y = __shfl_up_sync(0xffffffffu, x, o);
        if (lane >= o) x += y;
    }
    __shared__ int ws[8], wso[8];
    __shared__ int sh_total, sh_excl;
    if (lane == 31) ws[w] = x;
    __syncthreads();
    if (t < 8) {
        int s = 0;
        for (int j = 0; j < t; j++) s += ws[j];
        wso[t] = s;
    }
    __syncthreads();
    const int incl = x + wso[w];
    if (t == 255) sh_total = incl;
    __syncthreads();
    const int total = sh_total;

    // publish aggregate (or prefix for block 0) ASAP
    if (t == 0) {
        if (bid == 0) {
            __threadfence();
            atomicExch(&g_scanPack[0], ((unsigned long long)total << 2) | 2ull);
            sh_excl = 0;
        } else {
            __threadfence();
            atomicExch(&g_scanPack[bid], ((unsigned long long)total << 2) | 1ull);
        }
    }
    __syncthreads();

    // warp 0 lookback (bid > 0): windowed 32-wide scan over predecessors
    if (bid > 0 && t < 32) {
        int excl = 0;
        int j = bid - 1;
        while (true) {
            int idx = j - lane;
            unsigned long long p = 0ull;
            int st = 0, val = 0;
            if (idx >= 0) {
                do {
                    p = atomicAdd(&g_scanPack[idx], 0ull);
                    st = (int)(p & 3ull);
                } while (st == 0);
                val = (int)(p >> 2);
            }
            unsigned pmask = __ballot_sync(0xffffffffu, idx >= 0 && st == 2);
            if (pmask) {
                int lead = __ffs(pmask) - 1;   // smallest lane = closest prefix
                int v = (lane <= lead) ? val : 0;
                #pragma unroll
                for (int o = 16; o; o >>= 1) v += __shfl_down_sync(0xffffffffu, v, o);
                if (lane == 0) excl += v;
                break;
            } else {
                int v = (idx >= 0) ? val : 0;
                #pragma unroll
                for (int o = 16; o; o >>= 1) v += __shfl_down_sync(0xffffffffu, v, o);
                if (lane == 0) excl += v;
                j -= 32;
            }
        }
        if (lane == 0) {
            __threadfence();
            atomicExch(&g_scanPack[bid],
                       ((unsigned long long)(excl + total) << 2) | 2ull);
            sh_excl = excl;
        }
    }
    __syncthreads();

    g_offsets[i] = sh_excl + incl - c;
    g_dinv[i] = rsqrtf((float)(c + 1));
}

// scatter dst-sorted edge records {src, dinv[d]*dinv[s]} (needs g_dinv ready)
__global__ void scatter_kernel(const void* __restrict__ ei) {
    int e = blockIdx.x * blockDim.x + threadIdx.x;
    if (e < EE) {
        int d = ei_at(ei, (size_t)EE + e);
        int s = ei_at(ei, (size_t)e);
        int pos = g_offsets[d] + atomicAdd(&g_fill[d], 1);
        float w = g_dinv[d] * g_dinv[s];
        g_edge[pos] = make_int2(s, __float_as_int(w));
    }
}

// -------------------- fused misc prep: xconv + weight split + fc_init --------
#define XCSZ (NN * F_IN / 2)
#define W1SZ (F_IN * H1)
#define W2SZ (H1 * H2)
#define W3SZ (H2 * H3)
#define MISC_TOT (XCSZ + W1SZ + W2SZ + W3SZ + NG * OUTD)
__global__ void prep_misc(const float* __restrict__ x,
                          const float* __restrict__ W1,
                          const float* __restrict__ W2,
                          const float* __restrict__ W3,
                          const float* __restrict__ bfc,
                          float* __restrict__ out) {
    int i = blockIdx.x * blockDim.x + threadIdx.x;
    if (i < XCSZ) {
        float2 v = ((const float2*)x)[i];
        ((__half2*)g_hf)[i] = __floats2half2_rn(v.x, v.y);
        return;
    }
    i -= XCSZ;
    const float* src;
    __half* dh;
    __half* dl;
    if (i < W1SZ) { src = W1; dh = g_w1H; dl = g_w1L; }
    else if (i < W1SZ + W2SZ) { i -= W1SZ; src = W2; dh = g_w2H; dl = g_w2L; }
    else if (i < W1SZ + W2SZ + W3SZ) { i -= W1SZ + W2SZ; src = W3; dh = g_w3H; dl = g_w3L; }
    else {
        i -= W1SZ + W2SZ + W3SZ;
        if (i < NG * OUTD) out[i] = bfc[i & 63];
        return;
    }
    float v = src[i];
    __half h = __float2half_rn(v);
    dh[i] = h;
    dl[i] = __float2half_rn(v - __half2float(h));
}

// -------------------- agg1: fp16 x (H=128, g_hf) -> fp16 g_af ----------------
__global__ void agg1_kernel() {
    int gw = (blockIdx.x * blockDim.x + threadIdx.x) >> 5;
    int lane = threadIdx.x & 31;
    if (gw >= NN) return;
    const int n = gw;
    const float dd = g_dinv[n];
    const float w0 = dd * dd;

    float acc[4];
    {
        uint2 hv = ((const uint2*)(g_hf + (size_t)n * F_IN))[lane];
        float2 f0 = h2f2(hv.x), f1 = h2f2(hv.y);
        acc[0] = w0 * f0.x; acc[1] = w0 * f0.y;
        acc[2] = w0 * f1.x; acc[3] = w0 * f1.y;
    }

    const int e0 = g_offsets[n], e1 = g_offsets[n + 1];
    for (int e = e0; e < e1; e++) {
        int2 ew = g_edge[e];
        float w = __int_as_float(ew.y);
        uint2 hv = ((const uint2*)(g_hf + (size_t)ew.x * F_IN))[lane];
        float2 f0 = h2f2(hv.x), f1 = h2f2(hv.y);
        acc[0] += w * f0.x; acc[1] += w * f0.y;
        acc[2] += w * f1.x; acc[3] += w * f1.y;
    }

    __half2 o0 = __floats2half2_rn(acc[0], acc[1]);
    __half2 o1 = __floats2half2_rn(acc[2], acc[3]);
    ((uint2*)(g_af + (size_t)n * F_IN))[lane] =
        make_uint2(*(uint32_t*)&o0, *(uint32_t*)&o1);
}

// -------------------- agg2: fp16 (H=256, g_hf) -> fp16 g_af ------------------
__global__ void agg23_kernel() {
    int gw = (blockIdx.x * blockDim.x + threadIdx.x) >> 5;
    int lane = threadIdx.x & 31;
    if (gw >= NN) return;
    const int n = gw;
    const float dd = g_dinv[n];
    const float w0 = dd * dd;

    float acc[8];
    {
        uint4 hv = ((const uint4*)(g_hf + (size_t)n * 256))[lane];
        float2 f0 = h2f2(hv.x), f1 = h2f2(hv.y), f2 = h2f2(hv.z), f3 = h2f2(hv.w);
        acc[0] = w0 * f0.x; acc[1] = w0 * f0.y; acc[2] = w0 * f1.x; acc[3] = w0 * f1.y;
        acc[4] = w0 * f2.x; acc[5] = w0 * f2.y; acc[6] = w0 * f3.x; acc[7] = w0 * f3.y;
    }

    const int e0 = g_offsets[n], e1 = g_offsets[n + 1];
    for (int e = e0; e < e1; e++) {
        int2 ew = g_edge[e];
        float w = __int_as_float(ew.y);
        uint4 hv = ((const uint4*)(g_hf + (size_t)ew.x * 256))[lane];
        float2 f0 = h2f2(hv.x), f1 = h2f2(hv.y), f2 = h2f2(hv.z), f3 = h2f2(hv.w);
        acc[0] += w * f0.x; acc[1] += w * f0.y; acc[2] += w * f1.x; acc[3] += w * f1.y;
        acc[4] += w * f2.x; acc[5] += w * f2.y; acc[6] += w * f3.x; acc[7] += w * f3.y;
    }

    __half2 o0 = __floats2half2_rn(acc[0], acc[1]);
    __half2 o1 = __floats2half2_rn(acc[2], acc[3]);
    __half2 o2 = __floats2half2_rn(acc[4], acc[5]);
    __half2 o3 = __floats2half2_rn(acc[6], acc[7]);
    uint4 ov;
    ov.x = *(uint32_t*)&o0; ov.y = *(uint32_t*)&o1;
    ov.z = *(uint32_t*)&o2; ov.w = *(uint32_t*)&o3;
    ((uint4*)(g_af + (size_t)n * 256))[lane] = ov;
}

// -------- agg3: raw t3 (H=128, g_af) -> h3 = tanh(agg + b3) in g_hf ----------
__global__ void aggtanh_kernel(const float* __restrict__ bias) {
    int gw = (blockIdx.x * blockDim.x + threadIdx.x) >> 5;
    int lane = threadIdx.x & 31;
    if (gw >= NN) return;
    const int n = gw;
    const float dd = g_dinv[n];
    const float w0 = dd * dd;

    float acc[4];
    {
        uint2 hv = ((const uint2*)(g_af + (size_t)n * H3))[lane];
        float2 f0 = h2f2(hv.x), f1 = h2f2(hv.y);
        acc[0] = w0 * f0.x; acc[1] = w0 * f0.y;
        acc[2] = w0 * f1.x; acc[3] = w0 * f1.y;
    }

    const int e0 = g_offsets[n], e1 = g_offsets[n + 1];
    for (int e = e0; e < e1; e++) {
        int2 ew = g_edge[e];
        float w = __int_as_float(ew.y);
        uint2 hv = ((const uint2*)(g_af + (size_t)ew.x * H3))[lane];
        float2 f0 = h2f2(hv.x), f1 = h2f2(hv.y);
        acc[0] += w * f0.x; acc[1] += w * f0.y;
        acc[2] += w * f1.x; acc[3] += w * f1.y;
    }

    float4 b = ((const float4*)bias)[lane];
    float v0 = tanhf(acc[0] + b.x);
    float v1 = tanhf(acc[1] + b.y);
    float v2 = tanhf(acc[2] + b.z);
    float v3 = tanhf(acc[3] + b.w);
    __half2 o0 = __floats2half2_rn(v0, v1);
    __half2 o1 = __floats2half2_rn(v2, v3);
    ((uint2*)(g_hf + (size_t)n * H3))[lane] =
        make_uint2(*(uint32_t*)&o0, *(uint32_t*)&o1);
}

// -------------------- GEMM via mma.sync fp16, 3-stage cp.async, occ 2 --------
#define A_PITCH 80    // 32 fp16 = 64B + 16B pad
#define B_PITCH 272   // 128 fp16 = 256B + 16B pad
#define SM_A  0
#define SM_BH (128 * A_PITCH)
#define SM_BL (128 * A_PITCH + 32 * B_PITCH)
#define SM_STG (128 * A_PITCH + 2 * 32 * B_PITCH)   // 27648 B
#define SM_TOT (3 * SM_STG)                         // 82944 B

template <int K, int NB, int WSEL, int ASRC>
__device__ __forceinline__ void gemm_load_chunk(uint32_t sb, int stg, int m0, int n0,
                                                int k0, int t) {
    uint32_t base = sb + stg * SM_STG;
    const __half* A = ASRC ? g_hf : g_af;
    const __half* wH = wselH(WSEL);
    const __half* wL = wselL(WSEL);
    #pragma unroll
    for (int i = 0; i < 2; i++) {
        int idx = t + i * 256;
        int row = idx >> 2, seg = idx & 3;
        size_t gofs = ((size_t)(m0 + row) * K + k0) * 2 + seg * 16;
        cpa16(base + SM_A + row * A_PITCH + seg * 16, (const char*)A + gofs);
    }
    #pragma unroll
    for (int i = 0; i < 2; i++) {
        int idx = t + i * 256;
        int row = idx >> 4, seg = idx & 15;
        size_t gofs = ((size_t)(k0 + row) * NB + n0) * 2 + seg * 16;
        cpa16(base + SM_BH + row * B_PITCH + seg * 16, (const char*)wH + gofs);
        cpa16(base + SM_BL + row * B_PITCH + seg * 16, (const char*)wL + gofs);
    }
    CPA_COMMIT();
}

template <int K, int NB, int WSEL, int ASRC, int TANH>
__global__ void __launch_bounds__(256, 2)
gemm_mma(const float* __restrict__ bias) {
    extern __shared__ char sm[];
    const uint32_t sb = smem_u32(sm);
    const int t = threadIdx.x;
    const int warp = t >> 5, lane = t & 31;
    const int wm = warp >> 1, wn = warp & 1;
    const int m0 = blockIdx.y * 128, n0 = blockIdx.x * 128;
    constexpr int NCH = K / 32;

    float c[2][8][4];
    #pragma unroll
    for (int i = 0; i < 2; i++)
        #pragma unroll
        for (int j = 0; j < 8; j++)
            #pragma unroll
            for (int q = 0; q < 4; q++) c[i][j][q] = 0.0f;

    gemm_load_chunk<K, NB, WSEL, ASRC>(sb, 0, m0, n0, 0, t);
    gemm_load_chunk<K, NB, WSEL, ASRC>(sb, 1, m0, n0, 32, t);

    for (int ch = 0; ch < NCH; ch++) {
        if (ch + 1 < NCH) { CPA_WAIT1(); } else { CPA_WAIT0(); }
        __syncthreads();
        if (ch + 2 < NCH)
            gemm_load_chunk<K, NB, WSEL, ASRC>(sb, (ch + 2) % 3, m0, n0, (ch + 2) * 32, t);

        const char* base = sm + (ch % 3) * SM_STG;
        #pragma unroll
        for (int k16 = 0; k16 < 2; k16++) {
            uint32_t aa[2][4];
            #pragma unroll
            for (int mt = 0; mt < 2; mt++) {
                int row = wm * 32 + mt * 16 + (lane & 15);
                int cb = k16 * 32 + ((lane >> 4) << 4);
                LDSM_X4(aa[mt], smem_u32(base + SM_A + row * A_PITCH + cb));
            }
            uint32_t bh[4][4], bl[4][4];
            #pragma unroll
            for (int np = 0; np < 4; np++) {
                int krow = k16 * 16 + (lane & 7) + (lane & 8);
                int cb = wn * 128 + np * 32 + ((lane >> 4) << 4);
                LDSM_X4T(bh[np], smem_u32(base + SM_BH + krow * B_PITCH + cb));
                LDSM_X4T(bl[np], smem_u32(base + SM_BL + krow * B_PITCH + cb));
            }
            #pragma unroll
            for (int mt = 0; mt < 2; mt++) {
                #pragma unroll
                for (int np = 0; np < 4; np++) {
                    mma16816h(c[mt][np * 2],     aa[mt], bh[np][0], bh[np][1]);
                    mma16816h(c[mt][np * 2],     aa[mt], bl[np][0], bl[np][1]);
                    mma16816h(c[mt][np * 2 + 1], aa[mt], bh[np][2], bh[np][3]);
                    mma16816h(c[mt][np * 2 + 1], aa[mt], bl[np][2], bl[np][3]);
                }
            }
        }
        __syncthreads();
    }

    // epilogue: TANH -> tanh(acc+bias) into g_hf ; else raw fp16 into g_af
    const int g = lane >> 2, tq = lane & 3;
    __half* outp = TANH ? g_hf : g_af;
    #pragma unroll
    for (int mt = 0; mt < 2; mt++) {
        int row = m0 + wm * 32 + mt * 16 + g;
        #pragma unroll
        for (int n8 = 0; n8 < 8; n8++) {
            int col = n0 + wn * 64 + n8 * 8 + 2 * tq;
            float v0, v1, v2, v3;
            if (TANH) {
                float b0 = __ldg(bias + col), b1 = __ldg(bias + col + 1);
                v0 = tanhf(c[mt][n8][0] + b0);
                v1 = tanhf(c[mt][n8][1] + b1);
                v2 = tanhf(c[mt][n8][2] + b0);
                v3 = tanhf(c[mt][n8][3] + b1);
            } else {
                v0 = c[mt][n8][0]; v1 = c[mt][n8][1];
                v2 = c[mt][n8][2]; v3 = c[mt][n8][3];
            }
            *(__half2*)(outp + (size_t)row * NB + col) = __floats2half2_rn(v0, v1);
            *(__half2*)(outp + (size_t)(row + 8) * NB + col) = __floats2half2_rn(v2, v3);
        }
    }
}

// -------------------- final FC: out[64,64] = h3.reshape(64,128000) @ Wfc + bfc
#define FC_KCH 256
__global__ void fc_kernel(const float* __restrict__ Wfc,
                          float* __restrict__ out) {
    const __half* __restrict__ h3 = g_hf;   // fp16 h3 after aggtanh
    __shared__ float Ws[16][64];
    __shared__ float Hs[64][17];
    const int t = threadIdx.x;
    const int tg = t & 15;
    const int to = t >> 4;
    unsigned long long accp[4][2];
    #pragma unroll
    for (int i = 0; i < 4; i++) {
        accp[i][0] = 0ull;
        accp[i][1] = 0ull;
    }

    const int kbase = blockIdx.x * FC_KCH;
    for (int kk0 = 0; kk0 < FC_KCH; kk0 += 16) {
        const int k0 = kbase + kk0;
        #pragma unroll
        for (int rr = 0; rr < 4; rr++) {
            int idx = t + rr * 256;
            int kr = idx >> 6, nn = idx & 63;
            Ws[kr][nn] = Wfc[(size_t)(k0 + kr) * OUTD + nn];
        }
        #pragma unroll
        for (int rr = 0; rr < 4; rr++) {
            int idx = t + rr * 256;
            int g = idx >> 4, kk = idx & 15;
            Hs[g][kk] = __half2float(h3[(size_t)g * 128000 + k0 + kk]);
        }
        __syncthreads();
        #pragma unroll
        for (int kk = 0; kk < 16; kk++) {
            unsigned long long wvp[2];
            wvp[0] = pack2(Ws[kk][4 * to + 0], Ws[kk][4 * to + 1]);
            wvp[1] = pack2(Ws[kk][4 * to + 2], Ws[kk][4 * to + 3]);
            #pragma unroll
            for (int i = 0; i < 4; i++) {
                float hv = Hs[4 * tg + i][kk];
                unsigned long long hp = pack2(hv, hv);
                FFMA2(accp[i][0], hp, wvp[0]);
                FFMA2(accp[i][1], hp, wvp[1]);
            }
        }
        __syncthreads();
    }
    #pragma unroll
    for (int i = 0; i < 4; i++) {
        float a0, a1, a2, a3;
        unpack2(accp[i][0], a0, a1);
        unpack2(accp[i][1], a2, a3);
        float* op = &out[(4 * tg + i) * OUTD + 4 * to];
        atomicAdd(op + 0, a0);
        atomicAdd(op + 1, a1);
        atomicAdd(op + 2, a2);
        atomicAdd(op + 3, a3);
    }
}

// -------------------- launch --------------------
extern "C" void kernel_launch(void* const* d_in, const int* in_sizes, int n_in,
                              void* d_out, int out_size) {
    const float* x   = (const float*)d_in[0];
    const void*  ei  = d_in[1];
    const float* W1  = (const float*)d_in[3];
    const float* b1  = (const float*)d_in[4];
    const float* W2  = (const float*)d_in[5];
    const float* b2  = (const float*)d_in[6];
    const float* W3  = (const float*)d_in[7];
    const float* b3  = (const float*)d_in[8];
    const float* Wfc = (const float*)d_in[9];
    const float* bfc = (const float*)d_in[10];
    float* out = (float*)d_out;

    cudaFuncSetAttribute(gemm_mma<F_IN, H1, 1, 0, 1>, cudaFuncAttributeMaxDynamicSharedMemorySize, SM_TOT);
    cudaFuncSetAttribute(gemm_mma<H1, H2, 2, 0, 1>,   cudaFuncAttributeMaxDynamicSharedMemorySize, SM_TOT);
    cudaFuncSetAttribute(gemm_mma<H2, H3, 3, 1, 0>,   cudaFuncAttributeMaxDynamicSharedMemorySize, SM_TOT);

    // preprocessing (single stream; graph-capture-safe)
    zero_kernel<<<(NN / 4 + 255) / 256, 256>>>(ei);
    hist_kernel<<<EE / 256, 256>>>(ei);
    scan_kernel<<<NBLK, 256>>>();
    scatter_kernel<<<EE / 256, 256>>>(ei);
    prep_misc<<<(MISC_TOT + 255) / 256, 256>>>(x, W1, W2, W3, bfc, out);

    const int aggBlocks = (NN * 32) / 256;

    // layer 1: agg-first (Â x, 128) then GEMM(128->256), tanh -> g_hf
    agg1_kernel<<<aggBlocks, 256>>>();
    gemm_mma<F_IN, H1, 1, 0, 1><<<dim3(H1 / 128, NN / 128), 256, SM_TOT>>>(b1);

    // layer 2: agg (256) then GEMM(256->256), tanh -> g_hf
    agg23_kernel<<<aggBlocks, 256>>>();
    gemm_mma<H1, H2, 2, 0, 1><<<dim3(H2 / 128, NN / 128), 256, SM_TOT>>>(b2);

    // layer 3 (agg-after): GEMM(h2: 256->128) raw -> g_af, then agg(128)+b3+tanh -> g_hf
    gemm_mma<H2, H3, 3, 1, 0><<<dim3(H3 / 128, NN / 128), 256, SM_TOT>>>(nullptr);
    aggtanh_kernel<<<aggBlocks, 256>>>(b3);

    // final FC (fp16 h3, FFMA2) with split-K atomics
    fc_kernel<<<128000 / FC_KCH, 256>>>(Wfc, out);
}